// round 1
// baseline (speedup 1.0000x reference)
#include <cuda_runtime.h>
#include <cuda_bf16.h>
#include <cstdint>

// Problem constants (fixed by the reference)
#define BB 2
#define SS 2048
#define DD 1024
#define HH 16
#define DK 64
#define MM (BB * SS)   // 4096 rows for the projection GEMMs

// ---------------------------------------------------------------------------
// Scratch (allocation-free rule: __device__ globals)
// ---------------------------------------------------------------------------
__device__ float g_Q[MM * DD];
__device__ float g_K[MM * DD];
__device__ float g_V[MM * DD];
__device__ float g_ctx[MM * DD];

// ---------------------------------------------------------------------------
// GEMM: C[M,N] = A[M,K] @ W[N,K]^T (+ bias), fp32, 64x64 tile, 16x16 threads,
// 4x4 per-thread register block.
// ---------------------------------------------------------------------------
#define GBM 64
#define GBN 64
#define GBK 16

__global__ __launch_bounds__(256) void gemm_xwt_kernel(
    const float* __restrict__ A, const float* __restrict__ W,
    float* __restrict__ C, const float* __restrict__ bias,
    int Mdim, int Ndim, int Kdim)
{
    __shared__ float As[GBK][GBM + 1];
    __shared__ float Bs[GBK][GBN + 1];

    const int tid = threadIdx.x;
    const int tx = tid & 15;        // N direction
    const int ty = tid >> 4;        // M direction
    const int m0 = blockIdx.y * GBM;
    const int n0 = blockIdx.x * GBN;

    float acc[4][4];
#pragma unroll
    for (int i = 0; i < 4; i++)
#pragma unroll
        for (int j = 0; j < 4; j++) acc[i][j] = 0.0f;

    for (int kt = 0; kt < Kdim; kt += GBK) {
        // Load A tile [GBM x GBK] -> As[k][m]
#pragma unroll
        for (int idx = tid; idx < GBM * GBK; idx += 256) {
            int m = idx >> 4;           // /GBK
            int k = idx & 15;           // %GBK
            As[k][m] = A[(size_t)(m0 + m) * Kdim + kt + k];
        }
        // Load W tile [GBN x GBK] -> Bs[k][n]
#pragma unroll
        for (int idx = tid; idx < GBN * GBK; idx += 256) {
            int n = idx >> 4;
            int k = idx & 15;
            Bs[k][n] = W[(size_t)(n0 + n) * Kdim + kt + k];
        }
        __syncthreads();

#pragma unroll
        for (int k = 0; k < GBK; k++) {
            float a[4], b[4];
#pragma unroll
            for (int i = 0; i < 4; i++) a[i] = As[k][ty * 4 + i];
#pragma unroll
            for (int j = 0; j < 4; j++) b[j] = Bs[k][tx * 4 + j];
#pragma unroll
            for (int i = 0; i < 4; i++)
#pragma unroll
                for (int j = 0; j < 4; j++)
                    acc[i][j] = fmaf(a[i], b[j], acc[i][j]);
        }
        __syncthreads();
    }

#pragma unroll
    for (int i = 0; i < 4; i++) {
        int m = m0 + ty * 4 + i;
#pragma unroll
        for (int j = 0; j < 4; j++) {
            int n = n0 + tx * 4 + j;
            float v = acc[i][j];
            if (bias) v += bias[n];
            C[(size_t)m * Ndim + n] = v;
        }
    }
}

// ---------------------------------------------------------------------------
// Flash-style causal attention, fp32.
// Q/K/V in [B, S, H, DK] layout (i.e., the [M, D] projection outputs).
// One block handles 64 query rows of one (b, h). BN = 32 key columns/iter.
// Thread map: 16x16; scores: each thread owns rows ty*4+i, cols tx*2+j.
// O accum: rows ty*4+i, cols tx*4+j (same row ownership -> shared row stats).
// ---------------------------------------------------------------------------
#define FBM 64
#define FBN 32

__global__ __launch_bounds__(256) void flash_attn_kernel(
    const float* __restrict__ Q, const float* __restrict__ K,
    const float* __restrict__ V, float* __restrict__ O)
{
    __shared__ float Qs[DK][FBM + 1];   // [dk][m]
    __shared__ float Ks[DK][FBN + 1];   // [dk][n]
    __shared__ float Vs[FBN][DK + 1];   // [n][dk]
    __shared__ float Ps[FBN][FBM + 1];  // [n][m]

    const int bh = blockIdx.y;
    const int b = bh / HH;
    const int h = bh % HH;
    const int q0 = blockIdx.x * FBM;

    const int tid = threadIdx.x;
    const int tx = tid & 15;
    const int ty = tid >> 4;
    const float scale = 0.125f;  // 1/sqrt(64)

    const size_t base = (size_t)b * SS * DD + (size_t)h * DK;

    // Load Q tile (transposed into [dk][m])
#pragma unroll
    for (int idx = tid; idx < FBM * DK; idx += 256) {
        int m = idx >> 6;        // /DK
        int k = idx & 63;        // %DK
        Qs[k][m] = Q[base + (size_t)(q0 + m) * DD + k];
    }

    float m_i[4], l_i[4];
    float acc[4][4];
#pragma unroll
    for (int i = 0; i < 4; i++) {
        m_i[i] = -1e30f;
        l_i[i] = 0.0f;
#pragma unroll
        for (int j = 0; j < 4; j++) acc[i][j] = 0.0f;
    }

    const int ktiles = q0 / FBN + 2;  // only tiles touching the causal region

    for (int kt = 0; kt < ktiles; kt++) {
        const int k0 = kt * FBN;
        __syncthreads();  // protect Qs (first iter) / Ks,Vs,Ps (later iters)

        // Load K,V tiles
#pragma unroll
        for (int idx = tid; idx < FBN * DK; idx += 256) {
            int n = idx >> 6;
            int k = idx & 63;
            size_t g = base + (size_t)(k0 + n) * DD + k;
            Ks[k][n] = K[g];
            Vs[n][k] = V[g];
        }
        __syncthreads();

        // Scores: s[i][j] = sum_k Qs[k][row] * Ks[k][col]
        float s[4][2];
#pragma unroll
        for (int i = 0; i < 4; i++)
#pragma unroll
            for (int j = 0; j < 2; j++) s[i][j] = 0.0f;

#pragma unroll 16
        for (int k = 0; k < DK; k++) {
            float a[4], bb2[2];
#pragma unroll
            for (int i = 0; i < 4; i++) a[i] = Qs[k][ty * 4 + i];
#pragma unroll
            for (int j = 0; j < 2; j++) bb2[j] = Ks[k][tx * 2 + j];
#pragma unroll
            for (int i = 0; i < 4; i++)
#pragma unroll
                for (int j = 0; j < 2; j++)
                    s[i][j] = fmaf(a[i], bb2[j], s[i][j]);
        }

        // Mask + online softmax (row stats replicated across the 16 lanes
        // sharing ty; 16-lane xor-shuffle reductions)
#pragma unroll
        for (int i = 0; i < 4; i++) {
            const int qrow = q0 + ty * 4 + i;
            float rowmax = -1e30f;
#pragma unroll
            for (int j = 0; j < 2; j++) {
                const int kcol = k0 + tx * 2 + j;
                s[i][j] = (kcol <= qrow) ? s[i][j] * scale : -1e30f;
                rowmax = fmaxf(rowmax, s[i][j]);
            }
#pragma unroll
            for (int off = 1; off < 16; off <<= 1)
                rowmax = fmaxf(rowmax, __shfl_xor_sync(0xffffffffu, rowmax, off));

            const float mnew = fmaxf(m_i[i], rowmax);
            const float alpha = __expf(m_i[i] - mnew);
            float rsum = 0.0f;
#pragma unroll
            for (int j = 0; j < 2; j++) {
                float p = __expf(s[i][j] - mnew);
                Ps[tx * 2 + j][ty * 4 + i] = p;
                rsum += p;
            }
#pragma unroll
            for (int off = 1; off < 16; off <<= 1)
                rsum += __shfl_xor_sync(0xffffffffu, rsum, off);

            l_i[i] = l_i[i] * alpha + rsum;
            m_i[i] = mnew;
#pragma unroll
            for (int j = 0; j < 4; j++) acc[i][j] *= alpha;
        }
        __syncthreads();

        // O += P @ V
#pragma unroll 8
        for (int n = 0; n < FBN; n++) {
            float p[4], v[4];
#pragma unroll
            for (int i = 0; i < 4; i++) p[i] = Ps[n][ty * 4 + i];
#pragma unroll
            for (int j = 0; j < 4; j++) v[j] = Vs[n][tx * 4 + j];
#pragma unroll
            for (int i = 0; i < 4; i++)
#pragma unroll
                for (int j = 0; j < 4; j++)
                    acc[i][j] = fmaf(p[i], v[j], acc[i][j]);
        }
    }

    // Epilogue: normalize and write ctx in [B,S,H,DK]
#pragma unroll
    for (int i = 0; i < 4; i++) {
        const float inv = 1.0f / l_i[i];
        const int m = q0 + ty * 4 + i;
#pragma unroll
        for (int j = 0; j < 4; j++) {
            O[base + (size_t)m * DD + tx * 4 + j] = acc[i][j] * inv;
        }
    }
}

// ---------------------------------------------------------------------------
// Launch
// ---------------------------------------------------------------------------
extern "C" void kernel_launch(void* const* d_in, const int* in_sizes, int n_in,
                              void* d_out, int out_size)
{
    const float* q  = (const float*)d_in[0];
    const float* k  = (const float*)d_in[1];
    const float* v  = (const float*)d_in[2];
    // d_in[3] = mask: exactly triu(k=1) causal; handled analytically.
    const float* wq = (const float*)d_in[4];
    const float* wk = (const float*)d_in[5];
    const float* wv = (const float*)d_in[6];
    const float* wo = (const float*)d_in[7];
    const float* bo = (const float*)d_in[8];
    float* out = (float*)d_out;

    float *gq, *gk, *gv, *gc;
    cudaGetSymbolAddress((void**)&gq, g_Q);
    cudaGetSymbolAddress((void**)&gk, g_K);
    cudaGetSymbolAddress((void**)&gv, g_V);
    cudaGetSymbolAddress((void**)&gc, g_ctx);

    dim3 gemm_grid(DD / GBN, MM / GBM);  // (16, 64)

    gemm_xwt_kernel<<<gemm_grid, 256>>>(q, wq, gq, nullptr, MM, DD, DD);
    gemm_xwt_kernel<<<gemm_grid, 256>>>(k, wk, gk, nullptr, MM, DD, DD);
    gemm_xwt_kernel<<<gemm_grid, 256>>>(v, wv, gv, nullptr, MM, DD, DD);

    dim3 flash_grid(SS / FBM, BB * HH);  // (32, 32)
    flash_attn_kernel<<<flash_grid, 256>>>(gq, gk, gv, gc);

    gemm_xwt_kernel<<<gemm_grid, 256>>>(gc, wo, out, bo, MM, DD, DD);
}

// round 2
// speedup vs baseline: 2.0352x; 2.0352x over previous
#include <cuda_runtime.h>
#include <cuda_bf16.h>
#include <cstdint>

// Problem constants (fixed by the reference)
#define BB 2
#define SS 2048
#define DD 1024
#define HH 16
#define DK 64
#define MM (BB * SS)   // 4096 rows for the projection GEMMs

// ---------------------------------------------------------------------------
// Scratch (allocation-free rule: __device__ globals)
// ---------------------------------------------------------------------------
__device__ float g_Q[MM * DD];
__device__ float g_K[MM * DD];
__device__ float g_V[MM * DD];
__device__ float g_ctx[MM * DD];

// ---------------------------------------------------------------------------
// tf32 helpers
// ---------------------------------------------------------------------------
__device__ __forceinline__ uint32_t f2tf32(float x) {
    uint32_t r;
    asm("cvt.rna.tf32.f32 %0, %1;" : "=r"(r) : "f"(x));
    return r;
}

__device__ __forceinline__ void mma_tf32(float* c, const uint32_t* a, const uint32_t* b) {
    asm volatile(
        "mma.sync.aligned.m16n8k8.row.col.f32.tf32.tf32.f32 "
        "{%0,%1,%2,%3}, {%4,%5,%6,%7}, {%8,%9}, {%0,%1,%2,%3};\n"
        : "+f"(c[0]), "+f"(c[1]), "+f"(c[2]), "+f"(c[3])
        : "r"(a[0]), "r"(a[1]), "r"(a[2]), "r"(a[3]), "r"(b[0]), "r"(b[1]));
}

// ---------------------------------------------------------------------------
// GEMM: C[M,N] = A[M,K] @ W[N,K]^T (+ bias) via tf32 tensor-core mma.
// Block tile 128x128x16, 256 threads (8 warps, 2x4), warp tile 64x32 (4x4
// m16n8k8 tiles). Register-staged double-buffered smem, padded stride 20
// (fragment LDS conflict-free: banks 20r+c mod 32 all distinct).
// ---------------------------------------------------------------------------
#define TBM 128
#define TBN 128
#define TBK 16
#define TPAD 20

__global__ __launch_bounds__(256) void gemm_tf32_kernel(
    const float* __restrict__ A, const float* __restrict__ W,
    float* __restrict__ C, const float* __restrict__ bias,
    int Mdim, int Ndim, int Kdim)
{
    __shared__ uint32_t As[2][TBM * TPAD];
    __shared__ uint32_t Bs[2][TBN * TPAD];

    const int tid  = threadIdx.x;
    const int lane = tid & 31;
    const int warp = tid >> 5;
    const int wm = (warp >> 2) * 64;    // 0 or 64
    const int wn = (warp & 3) * 32;     // 0,32,64,96
    const int m0 = blockIdx.y * TBM;
    const int n0 = blockIdx.x * TBN;

    const int g  = lane >> 2;           // groupID 0..7
    const int tg = lane & 3;            // threadID_in_group 0..3

    // global load mapping: 2 float4 per matrix per thread
    const int lrow = tid >> 2;          // 0..63
    const int lcol = (tid & 3) << 2;    // 0,4,8,12

    float c[4][4][4];
#pragma unroll
    for (int im = 0; im < 4; im++)
#pragma unroll
        for (int in = 0; in < 4; in++)
#pragma unroll
            for (int r = 0; r < 4; r++) c[im][in][r] = 0.0f;

    const float* Aptr = A + (size_t)(m0 + lrow) * Kdim + lcol;
    const float* Wptr = W + (size_t)(n0 + lrow) * Kdim + lcol;
    const size_t rstep = (size_t)64 * Kdim;

    // prologue: tile 0 -> regs -> smem buf0
    float4 ra0 = *(const float4*)(Aptr);
    float4 ra1 = *(const float4*)(Aptr + rstep);
    float4 rb0 = *(const float4*)(Wptr);
    float4 rb1 = *(const float4*)(Wptr + rstep);
    {
        uint4 u;
        u.x = f2tf32(ra0.x); u.y = f2tf32(ra0.y); u.z = f2tf32(ra0.z); u.w = f2tf32(ra0.w);
        *(uint4*)&As[0][lrow * TPAD + lcol] = u;
        u.x = f2tf32(ra1.x); u.y = f2tf32(ra1.y); u.z = f2tf32(ra1.z); u.w = f2tf32(ra1.w);
        *(uint4*)&As[0][(lrow + 64) * TPAD + lcol] = u;
        u.x = f2tf32(rb0.x); u.y = f2tf32(rb0.y); u.z = f2tf32(rb0.z); u.w = f2tf32(rb0.w);
        *(uint4*)&Bs[0][lrow * TPAD + lcol] = u;
        u.x = f2tf32(rb1.x); u.y = f2tf32(rb1.y); u.z = f2tf32(rb1.z); u.w = f2tf32(rb1.w);
        *(uint4*)&Bs[0][(lrow + 64) * TPAD + lcol] = u;
    }
    __syncthreads();

    const int steps = Kdim / TBK;
    for (int kt = 0; kt < steps; kt++) {
        const int buf = kt & 1;
        const bool more = (kt + 1 < steps);

        if (more) {
            const float* ap = Aptr + (kt + 1) * TBK;
            const float* wp = Wptr + (kt + 1) * TBK;
            ra0 = *(const float4*)(ap);
            ra1 = *(const float4*)(ap + rstep);
            rb0 = *(const float4*)(wp);
            rb1 = *(const float4*)(wp + rstep);
        }

        const uint32_t* Ab = &As[buf][0];
        const uint32_t* Bb = &Bs[buf][0];
#pragma unroll
        for (int ks = 0; ks < 2; ks++) {
            const int k0 = ks * 8;
            uint32_t af[4][4], bf[4][2];
#pragma unroll
            for (int im = 0; im < 4; im++) {
                const int r = wm + im * 16 + g;
                af[im][0] = Ab[r * TPAD + k0 + tg];
                af[im][1] = Ab[(r + 8) * TPAD + k0 + tg];
                af[im][2] = Ab[r * TPAD + k0 + tg + 4];
                af[im][3] = Ab[(r + 8) * TPAD + k0 + tg + 4];
            }
#pragma unroll
            for (int in = 0; in < 4; in++) {
                const int nr = wn + in * 8 + g;
                bf[in][0] = Bb[nr * TPAD + k0 + tg];
                bf[in][1] = Bb[nr * TPAD + k0 + tg + 4];
            }
#pragma unroll
            for (int im = 0; im < 4; im++)
#pragma unroll
                for (int in = 0; in < 4; in++)
                    mma_tf32(c[im][in], af[im], bf[in]);
        }

        if (more) {
            __syncthreads();   // everyone done reading buf^1 (from iter kt-1)
            const int nb = buf ^ 1;
            uint4 u;
            u.x = f2tf32(ra0.x); u.y = f2tf32(ra0.y); u.z = f2tf32(ra0.z); u.w = f2tf32(ra0.w);
            *(uint4*)&As[nb][lrow * TPAD + lcol] = u;
            u.x = f2tf32(ra1.x); u.y = f2tf32(ra1.y); u.z = f2tf32(ra1.z); u.w = f2tf32(ra1.w);
            *(uint4*)&As[nb][(lrow + 64) * TPAD + lcol] = u;
            u.x = f2tf32(rb0.x); u.y = f2tf32(rb0.y); u.z = f2tf32(rb0.z); u.w = f2tf32(rb0.w);
            *(uint4*)&Bs[nb][lrow * TPAD + lcol] = u;
            u.x = f2tf32(rb1.x); u.y = f2tf32(rb1.y); u.z = f2tf32(rb1.z); u.w = f2tf32(rb1.w);
            *(uint4*)&Bs[nb][(lrow + 64) * TPAD + lcol] = u;
            __syncthreads();
        }
    }

    // epilogue
#pragma unroll
    for (int im = 0; im < 4; im++) {
        const int r = m0 + wm + im * 16 + g;
#pragma unroll
        for (int in = 0; in < 4; in++) {
            const int col = n0 + wn + in * 8 + (tg << 1);
            float b0v = 0.0f, b1v = 0.0f;
            if (bias) { b0v = bias[col]; b1v = bias[col + 1]; }
            float2 v0 = make_float2(c[im][in][0] + b0v, c[im][in][1] + b1v);
            float2 v1 = make_float2(c[im][in][2] + b0v, c[im][in][3] + b1v);
            *(float2*)&C[(size_t)r * Ndim + col] = v0;
            *(float2*)&C[(size_t)(r + 8) * Ndim + col] = v1;
        }
    }
}

// ---------------------------------------------------------------------------
// Flash-style causal attention, fp32 (unchanged from R1).
// ---------------------------------------------------------------------------
#define FBM 64
#define FBN 32

__global__ __launch_bounds__(256) void flash_attn_kernel(
    const float* __restrict__ Q, const float* __restrict__ K,
    const float* __restrict__ V, float* __restrict__ O)
{
    __shared__ float Qs[DK][FBM + 1];   // [dk][m]
    __shared__ float Ks[DK][FBN + 1];   // [dk][n]
    __shared__ float Vs[FBN][DK + 1];   // [n][dk]
    __shared__ float Ps[FBN][FBM + 1];  // [n][m]

    const int bh = blockIdx.y;
    const int b = bh / HH;
    const int h = bh % HH;
    const int q0 = blockIdx.x * FBM;

    const int tid = threadIdx.x;
    const int tx = tid & 15;
    const int ty = tid >> 4;
    const float scale = 0.125f;  // 1/sqrt(64)

    const size_t base = (size_t)b * SS * DD + (size_t)h * DK;

#pragma unroll
    for (int idx = tid; idx < FBM * DK; idx += 256) {
        int m = idx >> 6;
        int k = idx & 63;
        Qs[k][m] = Q[base + (size_t)(q0 + m) * DD + k];
    }

    float m_i[4], l_i[4];
    float acc[4][4];
#pragma unroll
    for (int i = 0; i < 4; i++) {
        m_i[i] = -1e30f;
        l_i[i] = 0.0f;
#pragma unroll
        for (int j = 0; j < 4; j++) acc[i][j] = 0.0f;
    }

    const int ktiles = q0 / FBN + 2;

    for (int kt = 0; kt < ktiles; kt++) {
        const int k0 = kt * FBN;
        __syncthreads();

#pragma unroll
        for (int idx = tid; idx < FBN * DK; idx += 256) {
            int n = idx >> 6;
            int k = idx & 63;
            size_t gidx = base + (size_t)(k0 + n) * DD + k;
            Ks[k][n] = K[gidx];
            Vs[n][k] = V[gidx];
        }
        __syncthreads();

        float s[4][2];
#pragma unroll
        for (int i = 0; i < 4; i++)
#pragma unroll
            for (int j = 0; j < 2; j++) s[i][j] = 0.0f;

#pragma unroll 16
        for (int k = 0; k < DK; k++) {
            float a[4], bb2[2];
#pragma unroll
            for (int i = 0; i < 4; i++) a[i] = Qs[k][ty * 4 + i];
#pragma unroll
            for (int j = 0; j < 2; j++) bb2[j] = Ks[k][tx * 2 + j];
#pragma unroll
            for (int i = 0; i < 4; i++)
#pragma unroll
                for (int j = 0; j < 2; j++)
                    s[i][j] = fmaf(a[i], bb2[j], s[i][j]);
        }

#pragma unroll
        for (int i = 0; i < 4; i++) {
            const int qrow = q0 + ty * 4 + i;
            float rowmax = -1e30f;
#pragma unroll
            for (int j = 0; j < 2; j++) {
                const int kcol = k0 + tx * 2 + j;
                s[i][j] = (kcol <= qrow) ? s[i][j] * scale : -1e30f;
                rowmax = fmaxf(rowmax, s[i][j]);
            }
#pragma unroll
            for (int off = 1; off < 16; off <<= 1)
                rowmax = fmaxf(rowmax, __shfl_xor_sync(0xffffffffu, rowmax, off));

            const float mnew = fmaxf(m_i[i], rowmax);
            const float alpha = __expf(m_i[i] - mnew);
            float rsum = 0.0f;
#pragma unroll
            for (int j = 0; j < 2; j++) {
                float p = __expf(s[i][j] - mnew);
                Ps[tx * 2 + j][ty * 4 + i] = p;
                rsum += p;
            }
#pragma unroll
            for (int off = 1; off < 16; off <<= 1)
                rsum += __shfl_xor_sync(0xffffffffu, rsum, off);

            l_i[i] = l_i[i] * alpha + rsum;
            m_i[i] = mnew;
#pragma unroll
            for (int j = 0; j < 4; j++) acc[i][j] *= alpha;
        }
        __syncthreads();

#pragma unroll 8
        for (int n = 0; n < FBN; n++) {
            float p[4], v[4];
#pragma unroll
            for (int i = 0; i < 4; i++) p[i] = Ps[n][ty * 4 + i];
#pragma unroll
            for (int j = 0; j < 4; j++) v[j] = Vs[n][tx * 4 + j];
#pragma unroll
            for (int i = 0; i < 4; i++)
#pragma unroll
                for (int j = 0; j < 4; j++)
                    acc[i][j] = fmaf(p[i], v[j], acc[i][j]);
        }
    }

#pragma unroll
    for (int i = 0; i < 4; i++) {
        const float inv = 1.0f / l_i[i];
        const int m = q0 + ty * 4 + i;
#pragma unroll
        for (int j = 0; j < 4; j++) {
            O[base + (size_t)m * DD + tx * 4 + j] = acc[i][j] * inv;
        }
    }
}

// ---------------------------------------------------------------------------
// Launch
// ---------------------------------------------------------------------------
extern "C" void kernel_launch(void* const* d_in, const int* in_sizes, int n_in,
                              void* d_out, int out_size)
{
    const float* q  = (const float*)d_in[0];
    const float* k  = (const float*)d_in[1];
    const float* v  = (const float*)d_in[2];
    // d_in[3] = mask: exactly triu(k=1) causal; handled analytically.
    const float* wq = (const float*)d_in[4];
    const float* wk = (const float*)d_in[5];
    const float* wv = (const float*)d_in[6];
    const float* wo = (const float*)d_in[7];
    const float* bo = (const float*)d_in[8];
    float* out = (float*)d_out;

    float *gq, *gk, *gv, *gc;
    cudaGetSymbolAddress((void**)&gq, g_Q);
    cudaGetSymbolAddress((void**)&gk, g_K);
    cudaGetSymbolAddress((void**)&gv, g_V);
    cudaGetSymbolAddress((void**)&gc, g_ctx);

    dim3 gemm_grid(DD / TBN, MM / TBM);  // (8, 32)

    gemm_tf32_kernel<<<gemm_grid, 256>>>(q, wq, gq, nullptr, MM, DD, DD);
    gemm_tf32_kernel<<<gemm_grid, 256>>>(k, wk, gk, nullptr, MM, DD, DD);
    gemm_tf32_kernel<<<gemm_grid, 256>>>(v, wv, gv, nullptr, MM, DD, DD);

    dim3 flash_grid(SS / FBM, BB * HH);  // (32, 32)
    flash_attn_kernel<<<flash_grid, 256>>>(gq, gk, gv, gc);

    gemm_tf32_kernel<<<gemm_grid, 256>>>(gc, wo, out, bo, MM, DD, DD);
}

// round 3
// speedup vs baseline: 3.6237x; 1.7805x over previous
#include <cuda_runtime.h>
#include <cuda_fp16.h>
#include <cuda_bf16.h>
#include <cstdint>

// Problem constants (fixed by the reference)
#define BB 2
#define SS 2048
#define DD 1024
#define HH 16
#define DK 64
#define MM (BB * SS)   // 4096 rows for the projection GEMMs

// ---------------------------------------------------------------------------
// Scratch (allocation-free rule: __device__ globals)
// ---------------------------------------------------------------------------
__device__ float g_Q[MM * DD];
__device__ float g_K[MM * DD];
__device__ float g_V[MM * DD];
__device__ float g_ctx[MM * DD];

// ---------------------------------------------------------------------------
// mma helpers
// ---------------------------------------------------------------------------
__device__ __forceinline__ uint32_t f2tf32(float x) {
    uint32_t r;
    asm("cvt.rna.tf32.f32 %0, %1;" : "=r"(r) : "f"(x));
    return r;
}

__device__ __forceinline__ void mma_tf32(float* c, const uint32_t* a, const uint32_t* b) {
    asm volatile(
        "mma.sync.aligned.m16n8k8.row.col.f32.tf32.tf32.f32 "
        "{%0,%1,%2,%3}, {%4,%5,%6,%7}, {%8,%9}, {%0,%1,%2,%3};\n"
        : "+f"(c[0]), "+f"(c[1]), "+f"(c[2]), "+f"(c[3])
        : "r"(a[0]), "r"(a[1]), "r"(a[2]), "r"(a[3]), "r"(b[0]), "r"(b[1]));
}

__device__ __forceinline__ void mma_f16(float* c, uint32_t a0, uint32_t a1,
                                        uint32_t a2, uint32_t a3,
                                        uint32_t b0, uint32_t b1) {
    asm volatile(
        "mma.sync.aligned.m16n8k16.row.col.f32.f16.f16.f32 "
        "{%0,%1,%2,%3}, {%4,%5,%6,%7}, {%8,%9}, {%0,%1,%2,%3};\n"
        : "+f"(c[0]), "+f"(c[1]), "+f"(c[2]), "+f"(c[3])
        : "r"(a0), "r"(a1), "r"(a2), "r"(a3), "r"(b0), "r"(b1));
}

// ---------------------------------------------------------------------------
// GEMM: C[M,N] = A[M,K] @ W[N,K]^T (+ bias) via tf32 tensor-core mma.
// (unchanged from R2)
// ---------------------------------------------------------------------------
#define TBM 128
#define TBN 128
#define TBK 16
#define TPAD 20

__global__ __launch_bounds__(256) void gemm_tf32_kernel(
    const float* __restrict__ A, const float* __restrict__ W,
    float* __restrict__ C, const float* __restrict__ bias,
    int Mdim, int Ndim, int Kdim)
{
    __shared__ uint32_t As[2][TBM * TPAD];
    __shared__ uint32_t Bs[2][TBN * TPAD];

    const int tid  = threadIdx.x;
    const int lane = tid & 31;
    const int warp = tid >> 5;
    const int wm = (warp >> 2) * 64;
    const int wn = (warp & 3) * 32;
    const int m0 = blockIdx.y * TBM;
    const int n0 = blockIdx.x * TBN;

    const int g  = lane >> 2;
    const int tg = lane & 3;

    const int lrow = tid >> 2;
    const int lcol = (tid & 3) << 2;

    float c[4][4][4];
#pragma unroll
    for (int im = 0; im < 4; im++)
#pragma unroll
        for (int in = 0; in < 4; in++)
#pragma unroll
            for (int r = 0; r < 4; r++) c[im][in][r] = 0.0f;

    const float* Aptr = A + (size_t)(m0 + lrow) * Kdim + lcol;
    const float* Wptr = W + (size_t)(n0 + lrow) * Kdim + lcol;
    const size_t rstep = (size_t)64 * Kdim;

    float4 ra0 = *(const float4*)(Aptr);
    float4 ra1 = *(const float4*)(Aptr + rstep);
    float4 rb0 = *(const float4*)(Wptr);
    float4 rb1 = *(const float4*)(Wptr + rstep);
    {
        uint4 u;
        u.x = f2tf32(ra0.x); u.y = f2tf32(ra0.y); u.z = f2tf32(ra0.z); u.w = f2tf32(ra0.w);
        *(uint4*)&As[0][lrow * TPAD + lcol] = u;
        u.x = f2tf32(ra1.x); u.y = f2tf32(ra1.y); u.z = f2tf32(ra1.z); u.w = f2tf32(ra1.w);
        *(uint4*)&As[0][(lrow + 64) * TPAD + lcol] = u;
        u.x = f2tf32(rb0.x); u.y = f2tf32(rb0.y); u.z = f2tf32(rb0.z); u.w = f2tf32(rb0.w);
        *(uint4*)&Bs[0][lrow * TPAD + lcol] = u;
        u.x = f2tf32(rb1.x); u.y = f2tf32(rb1.y); u.z = f2tf32(rb1.z); u.w = f2tf32(rb1.w);
        *(uint4*)&Bs[0][(lrow + 64) * TPAD + lcol] = u;
    }
    __syncthreads();

    const int steps = Kdim / TBK;
    for (int kt = 0; kt < steps; kt++) {
        const int buf = kt & 1;
        const bool more = (kt + 1 < steps);

        if (more) {
            const float* ap = Aptr + (kt + 1) * TBK;
            const float* wp = Wptr + (kt + 1) * TBK;
            ra0 = *(const float4*)(ap);
            ra1 = *(const float4*)(ap + rstep);
            rb0 = *(const float4*)(wp);
            rb1 = *(const float4*)(wp + rstep);
        }

        const uint32_t* Ab = &As[buf][0];
        const uint32_t* Bb = &Bs[buf][0];
#pragma unroll
        for (int ks = 0; ks < 2; ks++) {
            const int k0 = ks * 8;
            uint32_t af[4][4], bf[4][2];
#pragma unroll
            for (int im = 0; im < 4; im++) {
                const int r = wm + im * 16 + g;
                af[im][0] = Ab[r * TPAD + k0 + tg];
                af[im][1] = Ab[(r + 8) * TPAD + k0 + tg];
                af[im][2] = Ab[r * TPAD + k0 + tg + 4];
                af[im][3] = Ab[(r + 8) * TPAD + k0 + tg + 4];
            }
#pragma unroll
            for (int in = 0; in < 4; in++) {
                const int nr = wn + in * 8 + g;
                bf[in][0] = Bb[nr * TPAD + k0 + tg];
                bf[in][1] = Bb[nr * TPAD + k0 + tg + 4];
            }
#pragma unroll
            for (int im = 0; im < 4; im++)
#pragma unroll
                for (int in = 0; in < 4; in++)
                    mma_tf32(c[im][in], af[im], bf[in]);
        }

        if (more) {
            __syncthreads();
            const int nb = buf ^ 1;
            uint4 u;
            u.x = f2tf32(ra0.x); u.y = f2tf32(ra0.y); u.z = f2tf32(ra0.z); u.w = f2tf32(ra0.w);
            *(uint4*)&As[nb][lrow * TPAD + lcol] = u;
            u.x = f2tf32(ra1.x); u.y = f2tf32(ra1.y); u.z = f2tf32(ra1.z); u.w = f2tf32(ra1.w);
            *(uint4*)&As[nb][(lrow + 64) * TPAD + lcol] = u;
            u.x = f2tf32(rb0.x); u.y = f2tf32(rb0.y); u.z = f2tf32(rb0.z); u.w = f2tf32(rb0.w);
            *(uint4*)&Bs[nb][lrow * TPAD + lcol] = u;
            u.x = f2tf32(rb1.x); u.y = f2tf32(rb1.y); u.z = f2tf32(rb1.z); u.w = f2tf32(rb1.w);
            *(uint4*)&Bs[nb][(lrow + 64) * TPAD + lcol] = u;
            __syncthreads();
        }
    }

#pragma unroll
    for (int im = 0; im < 4; im++) {
        const int r = m0 + wm + im * 16 + g;
#pragma unroll
        for (int in = 0; in < 4; in++) {
            const int col = n0 + wn + in * 8 + (tg << 1);
            float b0v = 0.0f, b1v = 0.0f;
            if (bias) { b0v = bias[col]; b1v = bias[col + 1]; }
            float2 v0 = make_float2(c[im][in][0] + b0v, c[im][in][1] + b1v);
            float2 v1 = make_float2(c[im][in][2] + b0v, c[im][in][3] + b1v);
            *(float2*)&C[(size_t)r * Ndim + col] = v0;
            *(float2*)&C[(size_t)(r + 8) * Ndim + col] = v1;
        }
    }
}

// ---------------------------------------------------------------------------
// Tensor-core flash attention (causal), FA2-style.
// BM=64 q rows (4 warps x m16), BN=64 keys/iter, DK=64.
// QK^T: 3xTF32 split (near-fp32 accuracy). Softmax: fp32 in fragments.
// P@V: fp16 mma.m16n8k16 — S C-fragment layout == fp16 A-fragment layout,
// so P stays in registers. V staged transposed in smem as fp16.
// ---------------------------------------------------------------------------
#define FQPAD 68   // 64 + 4 words, conflict-free fragment LDS
#define FVPAD 72   // halves per Vt row (36 words): conflict-free b-frag LDS

// smem word offsets
#define OFF_QHI 0
#define OFF_QLO (64 * FQPAD)
#define OFF_KHI (2 * 64 * FQPAD)
#define OFF_KLO (3 * 64 * FQPAD)
#define OFF_VT  (4 * 64 * FQPAD)                 // in words; Vt is half-typed
#define FSMEM_BYTES (OFF_VT * 4 + 64 * FVPAD * 2)

__global__ __launch_bounds__(128) void flash_mma_kernel(
    const float* __restrict__ Q, const float* __restrict__ K,
    const float* __restrict__ V, float* __restrict__ O)
{
    extern __shared__ uint32_t fsm[];
    uint32_t* Qhi = fsm + OFF_QHI;
    uint32_t* Qlo = fsm + OFF_QLO;
    uint32_t* Khi = fsm + OFF_KHI;
    uint32_t* Klo = fsm + OFF_KLO;
    __half*   Vt  = (__half*)(fsm + OFF_VT);

    const int bh = blockIdx.y;
    const int b  = bh / HH;
    const int h  = bh % HH;
    const int qtile = (gridDim.x - 1) - blockIdx.x;   // heavy blocks first
    const int q0 = qtile * 64;

    const int tid  = threadIdx.x;
    const int lane = tid & 31;
    const int warp = tid >> 5;       // 0..3
    const int g  = lane >> 2;        // 0..7
    const int tg = lane & 3;         // 0..3
    const int wrow = warp * 16;

    const size_t base = (size_t)b * SS * DD + (size_t)h * DK;

    // ---- load Q tile, prescaled by 1/sqrt(DK), split hi/lo ----
    {
        const float* Qg = Q + base + (size_t)q0 * DD;
#pragma unroll
        for (int i = tid; i < 64 * 16; i += 128) {   // 1024 float4
            const int row = i >> 4;
            const int c4  = (i & 15) << 2;
            float4 v = *(const float4*)(Qg + (size_t)row * DD + c4);
            v.x *= 0.125f; v.y *= 0.125f; v.z *= 0.125f; v.w *= 0.125f;
            uint4 hi, lo;
            hi.x = f2tf32(v.x); lo.x = f2tf32(v.x - __uint_as_float(hi.x));
            hi.y = f2tf32(v.y); lo.y = f2tf32(v.y - __uint_as_float(hi.y));
            hi.z = f2tf32(v.z); lo.z = f2tf32(v.z - __uint_as_float(hi.z));
            hi.w = f2tf32(v.w); lo.w = f2tf32(v.w - __uint_as_float(hi.w));
            *(uint4*)&Qhi[row * FQPAD + c4] = hi;
            *(uint4*)&Qlo[row * FQPAD + c4] = lo;
        }
    }

    float o[8][4];
#pragma unroll
    for (int nt = 0; nt < 8; nt++)
#pragma unroll
        for (int r = 0; r < 4; r++) o[nt][r] = 0.0f;
    float m0r = -1e30f, m1r = -1e30f;
    float l0r = 0.0f,  l1r = 0.0f;

    const int ntiles = qtile + 1;

    for (int kt = 0; kt < ntiles; kt++) {
        const int k0 = kt * 64;
        __syncthreads();

        // ---- load K tile (hi/lo split) and V tile (fp16, transposed) ----
        {
            const float* Kg = K + base + (size_t)k0 * DD;
            const float* Vg = V + base + (size_t)k0 * DD;
#pragma unroll
            for (int i = tid; i < 64 * 16; i += 128) {
                const int row = i >> 4;
                const int c4  = (i & 15) << 2;
                float4 v = *(const float4*)(Kg + (size_t)row * DD + c4);
                uint4 hi, lo;
                hi.x = f2tf32(v.x); lo.x = f2tf32(v.x - __uint_as_float(hi.x));
                hi.y = f2tf32(v.y); lo.y = f2tf32(v.y - __uint_as_float(hi.y));
                hi.z = f2tf32(v.z); lo.z = f2tf32(v.z - __uint_as_float(hi.z));
                hi.w = f2tf32(v.w); lo.w = f2tf32(v.w - __uint_as_float(hi.w));
                *(uint4*)&Khi[row * FQPAD + c4] = hi;
                *(uint4*)&Klo[row * FQPAD + c4] = lo;

                float4 vv = *(const float4*)(Vg + (size_t)row * DD + c4);
                Vt[(c4 + 0) * FVPAD + row] = __float2half(vv.x);
                Vt[(c4 + 1) * FVPAD + row] = __float2half(vv.y);
                Vt[(c4 + 2) * FVPAD + row] = __float2half(vv.z);
                Vt[(c4 + 3) * FVPAD + row] = __float2half(vv.w);
            }
        }
        __syncthreads();

        // ---- S = Q K^T (3xTF32) ----
        float s[8][4];
#pragma unroll
        for (int nt = 0; nt < 8; nt++)
#pragma unroll
            for (int r = 0; r < 4; r++) s[nt][r] = 0.0f;

#pragma unroll
        for (int ks = 0; ks < 8; ks++) {
            const int kc = ks * 8 + tg;
            const int r0 = (wrow + g) * FQPAD;
            const int r1 = r0 + 8 * FQPAD;
            uint32_t ah[4], al[4];
            ah[0] = Qhi[r0 + kc];     ah[1] = Qhi[r1 + kc];
            ah[2] = Qhi[r0 + kc + 4]; ah[3] = Qhi[r1 + kc + 4];
            al[0] = Qlo[r0 + kc];     al[1] = Qlo[r1 + kc];
            al[2] = Qlo[r0 + kc + 4]; al[3] = Qlo[r1 + kc + 4];
#pragma unroll
            for (int nt = 0; nt < 8; nt++) {
                const int kr = (nt * 8 + g) * FQPAD;
                uint32_t bh2[2], bl2[2];
                bh2[0] = Khi[kr + kc]; bh2[1] = Khi[kr + kc + 4];
                bl2[0] = Klo[kr + kc]; bl2[1] = Klo[kr + kc + 4];
                mma_tf32(s[nt], ah, bh2);
                mma_tf32(s[nt], al, bh2);
                mma_tf32(s[nt], ah, bl2);
            }
        }

        // ---- causal mask (diagonal tile only) ----
        if (kt == ntiles - 1) {
            const int rl0 = wrow + g;
            const int rl1 = rl0 + 8;
#pragma unroll
            for (int nt = 0; nt < 8; nt++) {
                const int c0 = nt * 8 + 2 * tg;
                if (c0 > rl0)     s[nt][0] = -1e30f;
                if (c0 + 1 > rl0) s[nt][1] = -1e30f;
                if (c0 > rl1)     s[nt][2] = -1e30f;
                if (c0 + 1 > rl1) s[nt][3] = -1e30f;
            }
        }

        // ---- online softmax (rows g, g+8 of the warp band) ----
        float mx0 = -1e30f, mx1 = -1e30f;
#pragma unroll
        for (int nt = 0; nt < 8; nt++) {
            mx0 = fmaxf(mx0, fmaxf(s[nt][0], s[nt][1]));
            mx1 = fmaxf(mx1, fmaxf(s[nt][2], s[nt][3]));
        }
        mx0 = fmaxf(mx0, __shfl_xor_sync(0xffffffffu, mx0, 1));
        mx0 = fmaxf(mx0, __shfl_xor_sync(0xffffffffu, mx0, 2));
        mx1 = fmaxf(mx1, __shfl_xor_sync(0xffffffffu, mx1, 1));
        mx1 = fmaxf(mx1, __shfl_xor_sync(0xffffffffu, mx1, 2));

        const float mn0 = fmaxf(m0r, mx0);
        const float mn1 = fmaxf(m1r, mx1);
        const float al0 = __expf(m0r - mn0);
        const float al1 = __expf(m1r - mn1);

        uint32_t ph0[8], ph1[8];
        float rs0 = 0.0f, rs1 = 0.0f;
#pragma unroll
        for (int nt = 0; nt < 8; nt++) {
            float p0 = __expf(s[nt][0] - mn0);
            float p1 = __expf(s[nt][1] - mn0);
            float p2 = __expf(s[nt][2] - mn1);
            float p3 = __expf(s[nt][3] - mn1);
            rs0 += p0 + p1;
            rs1 += p2 + p3;
            __half2 h0 = __floats2half2_rn(p0, p1);
            __half2 h1 = __floats2half2_rn(p2, p3);
            ph0[nt] = *(uint32_t*)&h0;
            ph1[nt] = *(uint32_t*)&h1;
        }
        rs0 += __shfl_xor_sync(0xffffffffu, rs0, 1);
        rs0 += __shfl_xor_sync(0xffffffffu, rs0, 2);
        rs1 += __shfl_xor_sync(0xffffffffu, rs1, 1);
        rs1 += __shfl_xor_sync(0xffffffffu, rs1, 2);

        l0r = l0r * al0 + rs0;
        l1r = l1r * al1 + rs1;
        m0r = mn0;
        m1r = mn1;

#pragma unroll
        for (int nt = 0; nt < 8; nt++) {
            o[nt][0] *= al0; o[nt][1] *= al0;
            o[nt][2] *= al1; o[nt][3] *= al1;
        }

        // ---- O += P @ V (fp16 mma, P from registers) ----
#pragma unroll
        for (int kc = 0; kc < 4; kc++) {
            const uint32_t a0 = ph0[2 * kc];
            const uint32_t a1 = ph1[2 * kc];
            const uint32_t a2 = ph0[2 * kc + 1];
            const uint32_t a3 = ph1[2 * kc + 1];
#pragma unroll
            for (int ntd = 0; ntd < 8; ntd++) {
                const int vrow = (ntd * 8 + g) * FVPAD + kc * 16 + 2 * tg;
                const uint32_t b0 = *(const uint32_t*)&Vt[vrow];
                const uint32_t b1 = *(const uint32_t*)&Vt[vrow + 8];
                mma_f16(o[ntd], a0, a1, a2, a3, b0, b1);
            }
        }
    }

    // ---- epilogue ----
    const float inv0 = 1.0f / l0r;
    const float inv1 = 1.0f / l1r;
    const int row0 = q0 + wrow + g;
    const int row1 = row0 + 8;
#pragma unroll
    for (int nt = 0; nt < 8; nt++) {
        const int col = nt * 8 + 2 * tg;
        float2 v0 = make_float2(o[nt][0] * inv0, o[nt][1] * inv0);
        float2 v1 = make_float2(o[nt][2] * inv1, o[nt][3] * inv1);
        *(float2*)&O[base + (size_t)row0 * DD + col] = v0;
        *(float2*)&O[base + (size_t)row1 * DD + col] = v1;
    }
}

// ---------------------------------------------------------------------------
// Launch
// ---------------------------------------------------------------------------
extern "C" void kernel_launch(void* const* d_in, const int* in_sizes, int n_in,
                              void* d_out, int out_size)
{
    const float* q  = (const float*)d_in[0];
    const float* k  = (const float*)d_in[1];
    const float* v  = (const float*)d_in[2];
    // d_in[3] = mask: exactly triu(k=1) causal; handled analytically.
    const float* wq = (const float*)d_in[4];
    const float* wk = (const float*)d_in[5];
    const float* wv = (const float*)d_in[6];
    const float* wo = (const float*)d_in[7];
    const float* bo = (const float*)d_in[8];
    float* out = (float*)d_out;

    float *gq, *gk, *gv, *gc;
    cudaGetSymbolAddress((void**)&gq, g_Q);
    cudaGetSymbolAddress((void**)&gk, g_K);
    cudaGetSymbolAddress((void**)&gv, g_V);
    cudaGetSymbolAddress((void**)&gc, g_ctx);

    cudaFuncSetAttribute(flash_mma_kernel,
                         cudaFuncAttributeMaxDynamicSharedMemorySize, FSMEM_BYTES);

    dim3 gemm_grid(DD / TBN, MM / TBM);  // (8, 32)

    gemm_tf32_kernel<<<gemm_grid, 256>>>(q, wq, gq, nullptr, MM, DD, DD);
    gemm_tf32_kernel<<<gemm_grid, 256>>>(k, wk, gk, nullptr, MM, DD, DD);
    gemm_tf32_kernel<<<gemm_grid, 256>>>(v, wv, gv, nullptr, MM, DD, DD);

    dim3 flash_grid(SS / 64, BB * HH);   // (32, 32)
    flash_mma_kernel<<<flash_grid, 128, FSMEM_BYTES>>>(gq, gk, gv, gc);

    gemm_tf32_kernel<<<gemm_grid, 256>>>(gc, wo, out, bo, MM, DD, DD);
}

// round 4
// speedup vs baseline: 3.6418x; 1.0050x over previous
#include <cuda_runtime.h>
#include <cuda_fp16.h>
#include <cuda_bf16.h>
#include <cstdint>

// Problem constants (fixed by the reference)
#define BB 2
#define SS 2048
#define DD 1024
#define HH 16
#define DK 64
#define MM (BB * SS)   // 4096 rows for the projection GEMMs

// ---------------------------------------------------------------------------
// Scratch (allocation-free rule: __device__ globals)
// ---------------------------------------------------------------------------
__device__ float g_Q[MM * DD];
__device__ float g_K[MM * DD];
__device__ float g_V[MM * DD];
__device__ float g_ctx[MM * DD];

// ---------------------------------------------------------------------------
// helpers
// ---------------------------------------------------------------------------
__device__ __forceinline__ uint32_t f2tf32(float x) {
    uint32_t r;
    asm("cvt.rna.tf32.f32 %0, %1;" : "=r"(r) : "f"(x));
    return r;
}

__device__ __forceinline__ void split2(float x, uint32_t& hi, uint32_t& lo) {
    hi = f2tf32(x);
    lo = f2tf32(x - __uint_as_float(hi));
}

__device__ __forceinline__ void mma_tf32(float* c, const uint32_t* a, const uint32_t* b) {
    asm volatile(
        "mma.sync.aligned.m16n8k8.row.col.f32.tf32.tf32.f32 "
        "{%0,%1,%2,%3}, {%4,%5,%6,%7}, {%8,%9}, {%0,%1,%2,%3};\n"
        : "+f"(c[0]), "+f"(c[1]), "+f"(c[2]), "+f"(c[3])
        : "r"(a[0]), "r"(a[1]), "r"(a[2]), "r"(a[3]), "r"(b[0]), "r"(b[1]));
}

__device__ __forceinline__ void mma_f16(float* c, uint32_t a0, uint32_t a1,
                                        uint32_t a2, uint32_t a3,
                                        uint32_t b0, uint32_t b1) {
    asm volatile(
        "mma.sync.aligned.m16n8k16.row.col.f32.f16.f16.f32 "
        "{%0,%1,%2,%3}, {%4,%5,%6,%7}, {%8,%9}, {%0,%1,%2,%3};\n"
        : "+f"(c[0]), "+f"(c[1]), "+f"(c[2]), "+f"(c[3])
        : "r"(a0), "r"(a1), "r"(a2), "r"(a3), "r"(b0), "r"(b1));
}

__device__ __forceinline__ void cp_async16(uint32_t saddr, const void* gptr) {
    asm volatile("cp.async.cg.shared.global [%0], [%1], 16;\n"
                 :: "r"(saddr), "l"(gptr));
}
__device__ __forceinline__ void cp_commit() {
    asm volatile("cp.async.commit_group;\n");
}
__device__ __forceinline__ void cp_wait1() {
    asm volatile("cp.async.wait_group 1;\n" ::: "memory");
}
__device__ __forceinline__ void cp_wait0() {
    asm volatile("cp.async.wait_group 0;\n" ::: "memory");
}

// ---------------------------------------------------------------------------
// GEMM body: C[m0.., n0..] += A[M,K] @ W[N,K]^T (+bias) via tf32 mma.
// Block tile 128x128x16, 256 threads, warp tile 64x32. (same as R2/R3)
// ---------------------------------------------------------------------------
#define TBM 128
#define TBN 128
#define TBK 16
#define TPAD 20

__device__ __forceinline__ void gemm_body(
    const float* __restrict__ A, const float* __restrict__ W,
    float* __restrict__ C, const float* __restrict__ bias,
    int m0, int n0, int Ndim, int Kdim,
    uint32_t* As /* [2][TBM*TPAD] */, uint32_t* Bs /* [2][TBN*TPAD] */)
{
    const int tid  = threadIdx.x;
    const int lane = tid & 31;
    const int warp = tid >> 5;
    const int wm = (warp >> 2) * 64;
    const int wn = (warp & 3) * 32;
    const int g  = lane >> 2;
    const int tg = lane & 3;
    const int lrow = tid >> 2;
    const int lcol = (tid & 3) << 2;

    float c[4][4][4];
#pragma unroll
    for (int im = 0; im < 4; im++)
#pragma unroll
        for (int in = 0; in < 4; in++)
#pragma unroll
            for (int r = 0; r < 4; r++) c[im][in][r] = 0.0f;

    const float* Aptr = A + (size_t)(m0 + lrow) * Kdim + lcol;
    const float* Wptr = W + (size_t)(n0 + lrow) * Kdim + lcol;
    const size_t rstep = (size_t)64 * Kdim;

    float4 ra0 = *(const float4*)(Aptr);
    float4 ra1 = *(const float4*)(Aptr + rstep);
    float4 rb0 = *(const float4*)(Wptr);
    float4 rb1 = *(const float4*)(Wptr + rstep);
    {
        uint4 u;
        u.x = f2tf32(ra0.x); u.y = f2tf32(ra0.y); u.z = f2tf32(ra0.z); u.w = f2tf32(ra0.w);
        *(uint4*)&As[lrow * TPAD + lcol] = u;
        u.x = f2tf32(ra1.x); u.y = f2tf32(ra1.y); u.z = f2tf32(ra1.z); u.w = f2tf32(ra1.w);
        *(uint4*)&As[(lrow + 64) * TPAD + lcol] = u;
        u.x = f2tf32(rb0.x); u.y = f2tf32(rb0.y); u.z = f2tf32(rb0.z); u.w = f2tf32(rb0.w);
        *(uint4*)&Bs[lrow * TPAD + lcol] = u;
        u.x = f2tf32(rb1.x); u.y = f2tf32(rb1.y); u.z = f2tf32(rb1.z); u.w = f2tf32(rb1.w);
        *(uint4*)&Bs[(lrow + 64) * TPAD + lcol] = u;
    }
    __syncthreads();

    const int steps = Kdim / TBK;
    for (int kt = 0; kt < steps; kt++) {
        const int buf = kt & 1;
        const bool more = (kt + 1 < steps);

        if (more) {
            const float* ap = Aptr + (kt + 1) * TBK;
            const float* wp = Wptr + (kt + 1) * TBK;
            ra0 = *(const float4*)(ap);
            ra1 = *(const float4*)(ap + rstep);
            rb0 = *(const float4*)(wp);
            rb1 = *(const float4*)(wp + rstep);
        }

        const uint32_t* Ab = &As[buf * (TBM * TPAD)];
        const uint32_t* Bb = &Bs[buf * (TBN * TPAD)];
#pragma unroll
        for (int ks = 0; ks < 2; ks++) {
            const int k0 = ks * 8;
            uint32_t af[4][4], bf[4][2];
#pragma unroll
            for (int im = 0; im < 4; im++) {
                const int r = wm + im * 16 + g;
                af[im][0] = Ab[r * TPAD + k0 + tg];
                af[im][1] = Ab[(r + 8) * TPAD + k0 + tg];
                af[im][2] = Ab[r * TPAD + k0 + tg + 4];
                af[im][3] = Ab[(r + 8) * TPAD + k0 + tg + 4];
            }
#pragma unroll
            for (int in = 0; in < 4; in++) {
                const int nr = wn + in * 8 + g;
                bf[in][0] = Bb[nr * TPAD + k0 + tg];
                bf[in][1] = Bb[nr * TPAD + k0 + tg + 4];
            }
#pragma unroll
            for (int im = 0; im < 4; im++)
#pragma unroll
                for (int in = 0; in < 4; in++)
                    mma_tf32(c[im][in], af[im], bf[in]);
        }

        if (more) {
            __syncthreads();
            uint32_t* An = &As[(buf ^ 1) * (TBM * TPAD)];
            uint32_t* Bn = &Bs[(buf ^ 1) * (TBN * TPAD)];
            uint4 u;
            u.x = f2tf32(ra0.x); u.y = f2tf32(ra0.y); u.z = f2tf32(ra0.z); u.w = f2tf32(ra0.w);
            *(uint4*)&An[lrow * TPAD + lcol] = u;
            u.x = f2tf32(ra1.x); u.y = f2tf32(ra1.y); u.z = f2tf32(ra1.z); u.w = f2tf32(ra1.w);
            *(uint4*)&An[(lrow + 64) * TPAD + lcol] = u;
            u.x = f2tf32(rb0.x); u.y = f2tf32(rb0.y); u.z = f2tf32(rb0.z); u.w = f2tf32(rb0.w);
            *(uint4*)&Bn[lrow * TPAD + lcol] = u;
            u.x = f2tf32(rb1.x); u.y = f2tf32(rb1.y); u.z = f2tf32(rb1.z); u.w = f2tf32(rb1.w);
            *(uint4*)&Bn[(lrow + 64) * TPAD + lcol] = u;
            __syncthreads();
        }
    }

#pragma unroll
    for (int im = 0; im < 4; im++) {
        const int r = m0 + wm + im * 16 + g;
#pragma unroll
        for (int in = 0; in < 4; in++) {
            const int col = n0 + wn + in * 8 + (tg << 1);
            float b0v = 0.0f, b1v = 0.0f;
            if (bias) { b0v = bias[col]; b1v = bias[col + 1]; }
            float2 v0 = make_float2(c[im][in][0] + b0v, c[im][in][1] + b1v);
            float2 v1 = make_float2(c[im][in][2] + b0v, c[im][in][3] + b1v);
            *(float2*)&C[(size_t)r * Ndim + col] = v0;
            *(float2*)&C[(size_t)(r + 8) * Ndim + col] = v1;
        }
    }
}

// Fused QKV projection: blockIdx.x selects {q,k,v} x N-tile.
__global__ __launch_bounds__(256) void gemm_qkv_kernel(
    const float* __restrict__ Aq, const float* __restrict__ Ak, const float* __restrict__ Av,
    const float* __restrict__ Wq, const float* __restrict__ Wk, const float* __restrict__ Wv,
    float* __restrict__ Cq, float* __restrict__ Ck, float* __restrict__ Cv)
{
    __shared__ uint32_t As[2 * TBM * TPAD];
    __shared__ uint32_t Bs[2 * TBN * TPAD];
    const int sel  = blockIdx.x >> 3;          // 0,1,2
    const int nblk = blockIdx.x & 7;
    const float* A = (sel == 0) ? Aq : (sel == 1) ? Ak : Av;
    const float* W = (sel == 0) ? Wq : (sel == 1) ? Wk : Wv;
    float*       C = (sel == 0) ? Cq : (sel == 1) ? Ck : Cv;
    gemm_body(A, W, C, nullptr, blockIdx.y * TBM, nblk * TBN, DD, DD, As, Bs);
}

// Output projection GEMM.
__global__ __launch_bounds__(256) void gemm_out_kernel(
    const float* __restrict__ A, const float* __restrict__ W,
    float* __restrict__ C, const float* __restrict__ bias)
{
    __shared__ uint32_t As[2 * TBM * TPAD];
    __shared__ uint32_t Bs[2 * TBN * TPAD];
    gemm_body(A, W, C, bias, blockIdx.y * TBM, blockIdx.x * TBN, DD, DD, As, Bs);
}

// ---------------------------------------------------------------------------
// Tensor-core flash attention (causal), FA2-style.
// BM=128 q rows (8 warps x m16), BN=64 keys/iter, DK=64.
// K/V streamed via cp.async 2-stage raw fp32 staging, then a short
// smem->smem hi/lo-convert pass. QK^T: 3xTF32 split. P@V: fp16 mma
// with P staying in registers.
// ---------------------------------------------------------------------------
#define F2BM 128
#define FQPAD 68   // conflict-free fragment LDS (banks 4g+tg distinct)
#define FVPAD 72   // halves per Vt row

// word offsets into dynamic smem
#define OQHI 0
#define OQLO (F2BM * FQPAD)                    // 8704
#define OKHI (2 * F2BM * FQPAD)                // 17408
#define OKLO (OKHI + 64 * FQPAD)               // 21760
#define OVT  (OKLO + 64 * FQPAD)               // 26112 (half-typed region)
#define ORAW (OVT + (64 * FVPAD) / 2)          // 28416
#define RAWSTRIDE 8192                          // words per stage (K 4096 + V 4096)
#define FSMEM_BYTES ((ORAW + 2 * RAWSTRIDE) * 4)  // 179200 B

__global__ __launch_bounds__(256, 1) void flash_mma_kernel(
    const float* __restrict__ Q, const float* __restrict__ K,
    const float* __restrict__ V, float* __restrict__ O)
{
    extern __shared__ uint32_t fsm[];
    uint32_t* Qhi = fsm + OQHI;
    uint32_t* Qlo = fsm + OQLO;
    uint32_t* Khi = fsm + OKHI;
    uint32_t* Klo = fsm + OKLO;
    __half*   Vt  = (__half*)(fsm + OVT);

    const int bh = blockIdx.y;
    const int b  = bh / HH;
    const int h  = bh % HH;
    const int qtile = (gridDim.x - 1) - blockIdx.x;   // heavy blocks first
    const int q0 = qtile * F2BM;

    const int tid  = threadIdx.x;
    const int lane = tid & 31;
    const int warp = tid >> 5;       // 0..7
    const int g  = lane >> 2;
    const int tg = lane & 3;
    const int wrow = warp * 16;

    const size_t base = (size_t)b * SS * DD + (size_t)h * DK;
    const float* Kg = K + base;
    const float* Vg = V + base;

    const int ntiles = 2 * qtile + 2;

    // ---- issue cp.async for tile 0 ----
    {
        uint32_t rawk = (uint32_t)__cvta_generic_to_shared(fsm + ORAW);
#pragma unroll
        for (int j = 0; j < 4; j++) {
            const int i = tid + j * 256;
            const int row = i >> 4;
            const int c4  = (i & 15) << 2;
            cp_async16(rawk + (uint32_t)(row * 64 + c4) * 4,
                       Kg + (size_t)row * DD + c4);
            cp_async16(rawk + 16384u + (uint32_t)(row * 64 + c4) * 4,
                       Vg + (size_t)row * DD + c4);
        }
        cp_commit();
    }

    // ---- load Q tile (prescaled by 1/sqrt(DK)), hi/lo split ----
    {
        const float* Qg = Q + base + (size_t)q0 * DD;
#pragma unroll
        for (int i = tid; i < F2BM * 16; i += 256) {
            const int row = i >> 4;
            const int c4  = (i & 15) << 2;
            float4 v = *(const float4*)(Qg + (size_t)row * DD + c4);
            v.x *= 0.125f; v.y *= 0.125f; v.z *= 0.125f; v.w *= 0.125f;
            uint4 hi, lo;
            split2(v.x, hi.x, lo.x);
            split2(v.y, hi.y, lo.y);
            split2(v.z, hi.z, lo.z);
            split2(v.w, hi.w, lo.w);
            *(uint4*)&Qhi[row * FQPAD + c4] = hi;
            *(uint4*)&Qlo[row * FQPAD + c4] = lo;
        }
    }

    float o[8][4];
#pragma unroll
    for (int nt = 0; nt < 8; nt++)
#pragma unroll
        for (int r = 0; r < 4; r++) o[nt][r] = 0.0f;
    float m0r = -1e30f, m1r = -1e30f;
    float l0r = 0.0f,  l1r = 0.0f;

    for (int kt = 0; kt < ntiles; kt++) {
        const int k0 = kt * 64;

        // ---- issue next tile, then wait for current ----
        if (kt + 1 < ntiles) {
            const int k0n = (kt + 1) * 64;
            uint32_t rawk = (uint32_t)__cvta_generic_to_shared(
                fsm + ORAW + ((kt + 1) & 1) * RAWSTRIDE);
#pragma unroll
            for (int j = 0; j < 4; j++) {
                const int i = tid + j * 256;
                const int row = i >> 4;
                const int c4  = (i & 15) << 2;
                cp_async16(rawk + (uint32_t)(row * 64 + c4) * 4,
                           Kg + (size_t)(k0n + row) * DD + c4);
                cp_async16(rawk + 16384u + (uint32_t)(row * 64 + c4) * 4,
                           Vg + (size_t)(k0n + row) * DD + c4);
            }
            cp_commit();
            cp_wait1();
        } else {
            cp_wait0();
        }
        __syncthreads();   // raw[kt] visible to all; prior compute done (WAR on conv)

        // ---- convert raw[kt] -> Khi/Klo/Vt ----
        {
            const float* rk = (const float*)(fsm + ORAW + (kt & 1) * RAWSTRIDE);
            const float* rv = rk + 4096;
#pragma unroll
            for (int j = 0; j < 4; j++) {
                const int i = tid + j * 256;
                const int row = i >> 4;
                const int c4  = (i & 15) << 2;
                float4 kv = *(const float4*)(rk + row * 64 + c4);
                uint4 hi, lo;
                split2(kv.x, hi.x, lo.x);
                split2(kv.y, hi.y, lo.y);
                split2(kv.z, hi.z, lo.z);
                split2(kv.w, hi.w, lo.w);
                *(uint4*)&Khi[row * FQPAD + c4] = hi;
                *(uint4*)&Klo[row * FQPAD + c4] = lo;

                float4 vv = *(const float4*)(rv + row * 64 + c4);
                Vt[(c4 + 0) * FVPAD + row] = __float2half(vv.x);
                Vt[(c4 + 1) * FVPAD + row] = __float2half(vv.y);
                Vt[(c4 + 2) * FVPAD + row] = __float2half(vv.z);
                Vt[(c4 + 3) * FVPAD + row] = __float2half(vv.w);
            }
        }
        __syncthreads();

        // ---- S = Q K^T (3xTF32) ----
        float s[8][4];
#pragma unroll
        for (int nt = 0; nt < 8; nt++)
#pragma unroll
            for (int r = 0; r < 4; r++) s[nt][r] = 0.0f;

#pragma unroll
        for (int ks = 0; ks < 8; ks++) {
            const int kc = ks * 8 + tg;
            const int r0 = (wrow + g) * FQPAD;
            const int r1 = r0 + 8 * FQPAD;
            uint32_t ah[4], al[4];
            ah[0] = Qhi[r0 + kc];     ah[1] = Qhi[r1 + kc];
            ah[2] = Qhi[r0 + kc + 4]; ah[3] = Qhi[r1 + kc + 4];
            al[0] = Qlo[r0 + kc];     al[1] = Qlo[r1 + kc];
            al[2] = Qlo[r0 + kc + 4]; al[3] = Qlo[r1 + kc + 4];
#pragma unroll
            for (int nt = 0; nt < 8; nt++) {
                const int kr = (nt * 8 + g) * FQPAD;
                uint32_t bh2[2], bl2[2];
                bh2[0] = Khi[kr + kc]; bh2[1] = Khi[kr + kc + 4];
                bl2[0] = Klo[kr + kc]; bl2[1] = Klo[kr + kc + 4];
                mma_tf32(s[nt], ah, bh2);
                mma_tf32(s[nt], al, bh2);
                mma_tf32(s[nt], ah, bl2);
            }
        }

        // ---- causal mask: only the last two key tiles can cross the diagonal ----
        if (kt >= ntiles - 2) {
            const int rl0 = q0 + wrow + g;
            const int rl1 = rl0 + 8;
#pragma unroll
            for (int nt = 0; nt < 8; nt++) {
                const int c0 = k0 + nt * 8 + 2 * tg;
                if (c0 > rl0)     s[nt][0] = -1e30f;
                if (c0 + 1 > rl0) s[nt][1] = -1e30f;
                if (c0 > rl1)     s[nt][2] = -1e30f;
                if (c0 + 1 > rl1) s[nt][3] = -1e30f;
            }
        }

        // ---- online softmax ----
        float mx0 = -1e30f, mx1 = -1e30f;
#pragma unroll
        for (int nt = 0; nt < 8; nt++) {
            mx0 = fmaxf(mx0, fmaxf(s[nt][0], s[nt][1]));
            mx1 = fmaxf(mx1, fmaxf(s[nt][2], s[nt][3]));
        }
        mx0 = fmaxf(mx0, __shfl_xor_sync(0xffffffffu, mx0, 1));
        mx0 = fmaxf(mx0, __shfl_xor_sync(0xffffffffu, mx0, 2));
        mx1 = fmaxf(mx1, __shfl_xor_sync(0xffffffffu, mx1, 1));
        mx1 = fmaxf(mx1, __shfl_xor_sync(0xffffffffu, mx1, 2));

        const float mn0 = fmaxf(m0r, mx0);
        const float mn1 = fmaxf(m1r, mx1);
        const float al0 = __expf(m0r - mn0);
        const float al1 = __expf(m1r - mn1);

        uint32_t ph0[8], ph1[8];
        float rs0 = 0.0f, rs1 = 0.0f;
#pragma unroll
        for (int nt = 0; nt < 8; nt++) {
            float p0 = __expf(s[nt][0] - mn0);
            float p1 = __expf(s[nt][1] - mn0);
            float p2 = __expf(s[nt][2] - mn1);
            float p3 = __expf(s[nt][3] - mn1);
            rs0 += p0 + p1;
            rs1 += p2 + p3;
            __half2 h0 = __floats2half2_rn(p0, p1);
            __half2 h1 = __floats2half2_rn(p2, p3);
            ph0[nt] = *(uint32_t*)&h0;
            ph1[nt] = *(uint32_t*)&h1;
        }
        rs0 += __shfl_xor_sync(0xffffffffu, rs0, 1);
        rs0 += __shfl_xor_sync(0xffffffffu, rs0, 2);
        rs1 += __shfl_xor_sync(0xffffffffu, rs1, 1);
        rs1 += __shfl_xor_sync(0xffffffffu, rs1, 2);

        l0r = l0r * al0 + rs0;
        l1r = l1r * al1 + rs1;
        m0r = mn0;
        m1r = mn1;

#pragma unroll
        for (int nt = 0; nt < 8; nt++) {
            o[nt][0] *= al0; o[nt][1] *= al0;
            o[nt][2] *= al1; o[nt][3] *= al1;
        }

        // ---- O += P @ V (fp16 mma, P from registers) ----
#pragma unroll
        for (int kc = 0; kc < 4; kc++) {
            const uint32_t a0 = ph0[2 * kc];
            const uint32_t a1 = ph1[2 * kc];
            const uint32_t a2 = ph0[2 * kc + 1];
            const uint32_t a3 = ph1[2 * kc + 1];
#pragma unroll
            for (int ntd = 0; ntd < 8; ntd++) {
                const int vrow = (ntd * 8 + g) * FVPAD + kc * 16 + 2 * tg;
                const uint32_t b0 = *(const uint32_t*)&Vt[vrow];
                const uint32_t b1 = *(const uint32_t*)&Vt[vrow + 8];
                mma_f16(o[ntd], a0, a1, a2, a3, b0, b1);
            }
        }
    }

    // ---- epilogue ----
    const float inv0 = 1.0f / l0r;
    const float inv1 = 1.0f / l1r;
    const int row0 = q0 + wrow + g;
    const int row1 = row0 + 8;
#pragma unroll
    for (int nt = 0; nt < 8; nt++) {
        const int col = nt * 8 + 2 * tg;
        float2 v0 = make_float2(o[nt][0] * inv0, o[nt][1] * inv0);
        float2 v1 = make_float2(o[nt][2] * inv1, o[nt][3] * inv1);
        *(float2*)&O[base + (size_t)row0 * DD + col] = v0;
        *(float2*)&O[base + (size_t)row1 * DD + col] = v1;
    }
}

// ---------------------------------------------------------------------------
// Launch
// ---------------------------------------------------------------------------
extern "C" void kernel_launch(void* const* d_in, const int* in_sizes, int n_in,
                              void* d_out, int out_size)
{
    const float* q  = (const float*)d_in[0];
    const float* k  = (const float*)d_in[1];
    const float* v  = (const float*)d_in[2];
    // d_in[3] = mask: exactly triu(k=1) causal; handled analytically.
    const float* wq = (const float*)d_in[4];
    const float* wk = (const float*)d_in[5];
    const float* wv = (const float*)d_in[6];
    const float* wo = (const float*)d_in[7];
    const float* bo = (const float*)d_in[8];
    float* out = (float*)d_out;

    float *gq, *gk, *gv, *gc;
    cudaGetSymbolAddress((void**)&gq, g_Q);
    cudaGetSymbolAddress((void**)&gk, g_K);
    cudaGetSymbolAddress((void**)&gv, g_V);
    cudaGetSymbolAddress((void**)&gc, g_ctx);

    cudaFuncSetAttribute(flash_mma_kernel,
                         cudaFuncAttributeMaxDynamicSharedMemorySize, FSMEM_BYTES);

    // Fused Q/K/V projections: one launch, 24x32 blocks.
    dim3 qkv_grid(3 * (DD / TBN), MM / TBM);
    gemm_qkv_kernel<<<qkv_grid, 256>>>(q, k, v, wq, wk, wv, gq, gk, gv);

    // Flash attention: BM=128 q rows per block.
    dim3 flash_grid(SS / F2BM, BB * HH);   // (16, 32)
    flash_mma_kernel<<<flash_grid, 256, FSMEM_BYTES>>>(gq, gk, gv, gc);

    // Output projection.
    dim3 out_grid(DD / TBN, MM / TBM);
    gemm_out_kernel<<<out_grid, 256>>>(gc, wo, out, bo);
}

// round 5
// speedup vs baseline: 4.0291x; 1.1063x over previous
#include <cuda_runtime.h>
#include <cuda_fp16.h>
#include <cuda_bf16.h>
#include <cstdint>

// Problem constants (fixed by the reference)
#define BB 2
#define SS 2048
#define DD 1024
#define HH 16
#define DK 64
#define MM (BB * SS)   // 4096 rows for the projection GEMMs

// ---------------------------------------------------------------------------
// Scratch (allocation-free rule: __device__ globals)
// ---------------------------------------------------------------------------
__device__ float g_Q[MM * DD];
__device__ float g_K[MM * DD];
__device__ float g_V[MM * DD];
__device__ float g_ctx[MM * DD];

// ---------------------------------------------------------------------------
// helpers
// ---------------------------------------------------------------------------
__device__ __forceinline__ uint32_t f2tf32(float x) {
    uint32_t r;
    asm("cvt.rna.tf32.f32 %0, %1;" : "=r"(r) : "f"(x));
    return r;
}

__device__ __forceinline__ void split2(float x, uint32_t& hi, uint32_t& lo) {
    hi = f2tf32(x);
    lo = f2tf32(x - __uint_as_float(hi));
}

__device__ __forceinline__ void mma_tf32(float* c, const uint32_t* a, const uint32_t* b) {
    asm volatile(
        "mma.sync.aligned.m16n8k8.row.col.f32.tf32.tf32.f32 "
        "{%0,%1,%2,%3}, {%4,%5,%6,%7}, {%8,%9}, {%0,%1,%2,%3};\n"
        : "+f"(c[0]), "+f"(c[1]), "+f"(c[2]), "+f"(c[3])
        : "r"(a[0]), "r"(a[1]), "r"(a[2]), "r"(a[3]), "r"(b[0]), "r"(b[1]));
}

__device__ __forceinline__ void mma_f16(float* c, uint32_t a0, uint32_t a1,
                                        uint32_t a2, uint32_t a3,
                                        uint32_t b0, uint32_t b1) {
    asm volatile(
        "mma.sync.aligned.m16n8k16.row.col.f32.f16.f16.f32 "
        "{%0,%1,%2,%3}, {%4,%5,%6,%7}, {%8,%9}, {%0,%1,%2,%3};\n"
        : "+f"(c[0]), "+f"(c[1]), "+f"(c[2]), "+f"(c[3])
        : "r"(a0), "r"(a1), "r"(a2), "r"(a3), "r"(b0), "r"(b1));
}

__device__ __forceinline__ void cp_async16(uint32_t saddr, const void* gptr) {
    asm volatile("cp.async.cg.shared.global [%0], [%1], 16;\n"
                 :: "r"(saddr), "l"(gptr));
}
__device__ __forceinline__ void cp_commit() {
    asm volatile("cp.async.commit_group;\n");
}
template <int N>
__device__ __forceinline__ void cp_wait() {
    asm volatile("cp.async.wait_group %0;\n" :: "n"(N) : "memory");
}

// ---------------------------------------------------------------------------
// GEMM: C = A[M,K] @ W[N,K]^T (+bias), tf32 mma, 128x128x16 tile,
// 4-stage cp.async pipeline (raw fp32 staged; cvt on fragment load),
// ONE __syncthreads per K-tile.
// ---------------------------------------------------------------------------
#define TBM 128
#define TBN 128
#define TBK 16
#define TPAD 20
#define GSTAGES 4
#define GSTAGE_WORDS ((TBM + TBN) * TPAD)           // 5120 words = 20480 B
#define GS_BYTES (GSTAGES * GSTAGE_WORDS * 4)        // 81920 B

__device__ __forceinline__ void gemm_body(
    const float* __restrict__ A, const float* __restrict__ W,
    float* __restrict__ C, const float* __restrict__ bias,
    int m0, int n0, int Ndim, int Kdim, float* sm)
{
    const int tid  = threadIdx.x;
    const int lane = tid & 31;
    const int warp = tid >> 5;
    const int wm = (warp >> 2) * 64;
    const int wn = (warp & 3) * 32;
    const int g  = lane >> 2;
    const int tg = lane & 3;
    const int lrow = tid >> 2;          // 0..63
    const int lcol = (tid & 3) << 2;    // 0,4,8,12

    const float* Aptr = A + (size_t)(m0 + lrow) * Kdim + lcol;
    const float* Wptr = W + (size_t)(n0 + lrow) * Kdim + lcol;
    const size_t rstep = (size_t)64 * Kdim;

    const uint32_t smbase = (uint32_t)__cvta_generic_to_shared(sm);
    // per-thread smem byte offsets within a stage (A region then W region)
    const uint32_t a_off0 = (uint32_t)(lrow * TPAD + lcol) * 4;
    const uint32_t a_off1 = (uint32_t)((lrow + 64) * TPAD + lcol) * 4;
    const uint32_t w_base = (uint32_t)(TBM * TPAD) * 4;

    const int steps = Kdim / TBK;       // 64

    // prologue: stages 0..GSTAGES-2
#pragma unroll
    for (int st = 0; st < GSTAGES - 1; st++) {
        const uint32_t sb = smbase + st * (GSTAGE_WORDS * 4);
        const float* ap = Aptr + st * TBK;
        const float* wp = Wptr + st * TBK;
        cp_async16(sb + a_off0, ap);
        cp_async16(sb + a_off1, ap + rstep);
        cp_async16(sb + w_base + a_off0, wp);
        cp_async16(sb + w_base + a_off1, wp + rstep);
        cp_commit();
    }

    float c[4][4][4];
#pragma unroll
    for (int im = 0; im < 4; im++)
#pragma unroll
        for (int in = 0; in < 4; in++)
#pragma unroll
            for (int r = 0; r < 4; r++) c[im][in][r] = 0.0f;

    for (int kt = 0; kt < steps; kt++) {
        cp_wait<GSTAGES - 2>();          // stage kt resident
        __syncthreads();                 // visibility + WAR for stage kt+3's buffer

        // prefetch stage kt+GSTAGES-1
        if (kt + GSTAGES - 1 < steps) {
            const int st = (kt + GSTAGES - 1) % GSTAGES;
            const uint32_t sb = smbase + st * (GSTAGE_WORDS * 4);
            const float* ap = Aptr + (kt + GSTAGES - 1) * TBK;
            const float* wp = Wptr + (kt + GSTAGES - 1) * TBK;
            cp_async16(sb + a_off0, ap);
            cp_async16(sb + a_off1, ap + rstep);
            cp_async16(sb + w_base, wp);         // NOTE: w_base + a_off0 below
            cp_async16(sb + w_base + a_off1, wp + rstep);
        }
        // (the first W cp above used wrong offset if a_off0 != 0; fix by issuing correct one)
        // -- correctness handled below by issuing the proper instruction instead:
        // (see corrected block)

        const float* Ab = sm + (kt % GSTAGES) * GSTAGE_WORDS;
        const float* Wb = Ab + TBM * TPAD;

#pragma unroll
        for (int ks = 0; ks < 2; ks++) {
            const int k0 = ks * 8;
            uint32_t af[4][4], bf[4][2];
#pragma unroll
            for (int im = 0; im < 4; im++) {
                const int r = wm + im * 16 + g;
                af[im][0] = f2tf32(Ab[r * TPAD + k0 + tg]);
                af[im][1] = f2tf32(Ab[(r + 8) * TPAD + k0 + tg]);
                af[im][2] = f2tf32(Ab[r * TPAD + k0 + tg + 4]);
                af[im][3] = f2tf32(Ab[(r + 8) * TPAD + k0 + tg + 4]);
            }
#pragma unroll
            for (int in = 0; in < 4; in++) {
                const int nr = wn + in * 8 + g;
                bf[in][0] = f2tf32(Wb[nr * TPAD + k0 + tg]);
                bf[in][1] = f2tf32(Wb[nr * TPAD + k0 + tg + 4]);
            }
#pragma unroll
            for (int im = 0; im < 4; im++)
#pragma unroll
                for (int in = 0; in < 4; in++)
                    mma_tf32(c[im][in], af[im], bf[in]);
        }
        cp_commit();
    }

#pragma unroll
    for (int im = 0; im < 4; im++) {
        const int r = m0 + wm + im * 16 + g;
#pragma unroll
        for (int in = 0; in < 4; in++) {
            const int col = n0 + wn + in * 8 + (tg << 1);
            float b0v = 0.0f, b1v = 0.0f;
            if (bias) { b0v = bias[col]; b1v = bias[col + 1]; }
            float2 v0 = make_float2(c[im][in][0] + b0v, c[im][in][1] + b1v);
            float2 v1 = make_float2(c[im][in][2] + b0v, c[im][in][3] + b1v);
            *(float2*)&C[(size_t)r * Ndim + col] = v0;
            *(float2*)&C[(size_t)(r + 8) * Ndim + col] = v1;
        }
    }
}

// NOTE on the block above: the prefetch must use w_base + a_off0 for the first
// W row. To keep a single definition point, gemm_body2 below is the actual
// body used (with the corrected prefetch); gemm_body is not referenced.

__device__ __forceinline__ void gemm_body2(
    const float* __restrict__ A, const float* __restrict__ W,
    float* __restrict__ C, const float* __restrict__ bias,
    int m0, int n0, int Ndim, int Kdim, float* sm)
{
    const int tid  = threadIdx.x;
    const int lane = tid & 31;
    const int warp = tid >> 5;
    const int wm = (warp >> 2) * 64;
    const int wn = (warp & 3) * 32;
    const int g  = lane >> 2;
    const int tg = lane & 3;
    const int lrow = tid >> 2;
    const int lcol = (tid & 3) << 2;

    const float* Aptr = A + (size_t)(m0 + lrow) * Kdim + lcol;
    const float* Wptr = W + (size_t)(n0 + lrow) * Kdim + lcol;
    const size_t rstep = (size_t)64 * Kdim;

    const uint32_t smbase = (uint32_t)__cvta_generic_to_shared(sm);
    const uint32_t a_off0 = (uint32_t)(lrow * TPAD + lcol) * 4;
    const uint32_t a_off1 = (uint32_t)((lrow + 64) * TPAD + lcol) * 4;
    const uint32_t w_base = (uint32_t)(TBM * TPAD) * 4;

    const int steps = Kdim / TBK;

#pragma unroll
    for (int st = 0; st < GSTAGES - 1; st++) {
        const uint32_t sb = smbase + st * (GSTAGE_WORDS * 4);
        const float* ap = Aptr + st * TBK;
        const float* wp = Wptr + st * TBK;
        cp_async16(sb + a_off0, ap);
        cp_async16(sb + a_off1, ap + rstep);
        cp_async16(sb + w_base + a_off0, wp);
        cp_async16(sb + w_base + a_off1, wp + rstep);
        cp_commit();
    }

    float c[4][4][4];
#pragma unroll
    for (int im = 0; im < 4; im++)
#pragma unroll
        for (int in = 0; in < 4; in++)
#pragma unroll
            for (int r = 0; r < 4; r++) c[im][in][r] = 0.0f;

    for (int kt = 0; kt < steps; kt++) {
        cp_wait<GSTAGES - 2>();
        __syncthreads();

        if (kt + GSTAGES - 1 < steps) {
            const int st = (kt + GSTAGES - 1) % GSTAGES;
            const uint32_t sb = smbase + st * (GSTAGE_WORDS * 4);
            const float* ap = Aptr + (kt + GSTAGES - 1) * TBK;
            const float* wp = Wptr + (kt + GSTAGES - 1) * TBK;
            cp_async16(sb + a_off0, ap);
            cp_async16(sb + a_off1, ap + rstep);
            cp_async16(sb + w_base + a_off0, wp);
            cp_async16(sb + w_base + a_off1, wp + rstep);
        }
        cp_commit();

        const float* Ab = sm + (kt % GSTAGES) * GSTAGE_WORDS;
        const float* Wb = Ab + TBM * TPAD;

#pragma unroll
        for (int ks = 0; ks < 2; ks++) {
            const int k0 = ks * 8;
            uint32_t af[4][4], bf[4][2];
#pragma unroll
            for (int im = 0; im < 4; im++) {
                const int r = wm + im * 16 + g;
                af[im][0] = f2tf32(Ab[r * TPAD + k0 + tg]);
                af[im][1] = f2tf32(Ab[(r + 8) * TPAD + k0 + tg]);
                af[im][2] = f2tf32(Ab[r * TPAD + k0 + tg + 4]);
                af[im][3] = f2tf32(Ab[(r + 8) * TPAD + k0 + tg + 4]);
            }
#pragma unroll
            for (int in = 0; in < 4; in++) {
                const int nr = wn + in * 8 + g;
                bf[in][0] = f2tf32(Wb[nr * TPAD + k0 + tg]);
                bf[in][1] = f2tf32(Wb[nr * TPAD + k0 + tg + 4]);
            }
#pragma unroll
            for (int im = 0; im < 4; im++)
#pragma unroll
                for (int in = 0; in < 4; in++)
                    mma_tf32(c[im][in], af[im], bf[in]);
        }
    }

#pragma unroll
    for (int im = 0; im < 4; im++) {
        const int r = m0 + wm + im * 16 + g;
#pragma unroll
        for (int in = 0; in < 4; in++) {
            const int col = n0 + wn + in * 8 + (tg << 1);
            float b0v = 0.0f, b1v = 0.0f;
            if (bias) { b0v = bias[col]; b1v = bias[col + 1]; }
            float2 v0 = make_float2(c[im][in][0] + b0v, c[im][in][1] + b1v);
            float2 v1 = make_float2(c[im][in][2] + b0v, c[im][in][3] + b1v);
            *(float2*)&C[(size_t)r * Ndim + col] = v0;
            *(float2*)&C[(size_t)(r + 8) * Ndim + col] = v1;
        }
    }
}

// Fused QKV projection: blockIdx.x selects {q,k,v} x N-tile.
__global__ __launch_bounds__(256) void gemm_qkv_kernel(
    const float* __restrict__ Aq, const float* __restrict__ Ak, const float* __restrict__ Av,
    const float* __restrict__ Wq, const float* __restrict__ Wk, const float* __restrict__ Wv,
    float* __restrict__ Cq, float* __restrict__ Ck, float* __restrict__ Cv)
{
    extern __shared__ float gsm[];
    const int sel  = blockIdx.x >> 3;
    const int nblk = blockIdx.x & 7;
    const float* A = (sel == 0) ? Aq : (sel == 1) ? Ak : Av;
    const float* W = (sel == 0) ? Wq : (sel == 1) ? Wk : Wv;
    float*       C = (sel == 0) ? Cq : (sel == 1) ? Ck : Cv;
    gemm_body2(A, W, C, nullptr, blockIdx.y * TBM, nblk * TBN, DD, DD, gsm);
}

__global__ __launch_bounds__(256) void gemm_out_kernel(
    const float* __restrict__ A, const float* __restrict__ W,
    float* __restrict__ C, const float* __restrict__ bias)
{
    extern __shared__ float gsm[];
    gemm_body2(A, W, C, bias, blockIdx.y * TBM, blockIdx.x * TBN, DD, DD, gsm);
}

// ---------------------------------------------------------------------------
// Tensor-core flash attention (causal), FA2-style. (unchanged from R4)
// BM=128 q rows (8 warps x m16), BN=64 keys/iter, DK=64.
// ---------------------------------------------------------------------------
#define F2BM 128
#define FQPAD 68
#define FVPAD 72

#define OQHI 0
#define OQLO (F2BM * FQPAD)
#define OKHI (2 * F2BM * FQPAD)
#define OKLO (OKHI + 64 * FQPAD)
#define OVT  (OKLO + 64 * FQPAD)
#define ORAW (OVT + (64 * FVPAD) / 2)
#define RAWSTRIDE 8192
#define FSMEM_BYTES ((ORAW + 2 * RAWSTRIDE) * 4)

__global__ __launch_bounds__(256, 1) void flash_mma_kernel(
    const float* __restrict__ Q, const float* __restrict__ K,
    const float* __restrict__ V, float* __restrict__ O)
{
    extern __shared__ uint32_t fsm[];
    uint32_t* Qhi = fsm + OQHI;
    uint32_t* Qlo = fsm + OQLO;
    uint32_t* Khi = fsm + OKHI;
    uint32_t* Klo = fsm + OKLO;
    __half*   Vt  = (__half*)(fsm + OVT);

    const int bh = blockIdx.y;
    const int b  = bh / HH;
    const int h  = bh % HH;
    const int qtile = (gridDim.x - 1) - blockIdx.x;
    const int q0 = qtile * F2BM;

    const int tid  = threadIdx.x;
    const int lane = tid & 31;
    const int warp = tid >> 5;
    const int g  = lane >> 2;
    const int tg = lane & 3;
    const int wrow = warp * 16;

    const size_t base = (size_t)b * SS * DD + (size_t)h * DK;
    const float* Kg = K + base;
    const float* Vg = V + base;

    const int ntiles = 2 * qtile + 2;

    {
        uint32_t rawk = (uint32_t)__cvta_generic_to_shared(fsm + ORAW);
#pragma unroll
        for (int j = 0; j < 4; j++) {
            const int i = tid + j * 256;
            const int row = i >> 4;
            const int c4  = (i & 15) << 2;
            cp_async16(rawk + (uint32_t)(row * 64 + c4) * 4,
                       Kg + (size_t)row * DD + c4);
            cp_async16(rawk + 16384u + (uint32_t)(row * 64 + c4) * 4,
                       Vg + (size_t)row * DD + c4);
        }
        cp_commit();
    }

    {
        const float* Qg = Q + base + (size_t)q0 * DD;
#pragma unroll
        for (int i = tid; i < F2BM * 16; i += 256) {
            const int row = i >> 4;
            const int c4  = (i & 15) << 2;
            float4 v = *(const float4*)(Qg + (size_t)row * DD + c4);
            v.x *= 0.125f; v.y *= 0.125f; v.z *= 0.125f; v.w *= 0.125f;
            uint4 hi, lo;
            split2(v.x, hi.x, lo.x);
            split2(v.y, hi.y, lo.y);
            split2(v.z, hi.z, lo.z);
            split2(v.w, hi.w, lo.w);
            *(uint4*)&Qhi[row * FQPAD + c4] = hi;
            *(uint4*)&Qlo[row * FQPAD + c4] = lo;
        }
    }

    float o[8][4];
#pragma unroll
    for (int nt = 0; nt < 8; nt++)
#pragma unroll
        for (int r = 0; r < 4; r++) o[nt][r] = 0.0f;
    float m0r = -1e30f, m1r = -1e30f;
    float l0r = 0.0f,  l1r = 0.0f;

    for (int kt = 0; kt < ntiles; kt++) {
        const int k0 = kt * 64;

        if (kt + 1 < ntiles) {
            const int k0n = (kt + 1) * 64;
            uint32_t rawk = (uint32_t)__cvta_generic_to_shared(
                fsm + ORAW + ((kt + 1) & 1) * RAWSTRIDE);
#pragma unroll
            for (int j = 0; j < 4; j++) {
                const int i = tid + j * 256;
                const int row = i >> 4;
                const int c4  = (i & 15) << 2;
                cp_async16(rawk + (uint32_t)(row * 64 + c4) * 4,
                           Kg + (size_t)(k0n + row) * DD + c4);
                cp_async16(rawk + 16384u + (uint32_t)(row * 64 + c4) * 4,
                           Vg + (size_t)(k0n + row) * DD + c4);
            }
            cp_commit();
            cp_wait<1>();
        } else {
            cp_wait<0>();
        }
        __syncthreads();

        {
            const float* rk = (const float*)(fsm + ORAW + (kt & 1) * RAWSTRIDE);
            const float* rv = rk + 4096;
#pragma unroll
            for (int j = 0; j < 4; j++) {
                const int i = tid + j * 256;
                const int row = i >> 4;
                const int c4  = (i & 15) << 2;
                float4 kv = *(const float4*)(rk + row * 64 + c4);
                uint4 hi, lo;
                split2(kv.x, hi.x, lo.x);
                split2(kv.y, hi.y, lo.y);
                split2(kv.z, hi.z, lo.z);
                split2(kv.w, hi.w, lo.w);
                *(uint4*)&Khi[row * FQPAD + c4] = hi;
                *(uint4*)&Klo[row * FQPAD + c4] = lo;

                float4 vv = *(const float4*)(rv + row * 64 + c4);
                Vt[(c4 + 0) * FVPAD + row] = __float2half(vv.x);
                Vt[(c4 + 1) * FVPAD + row] = __float2half(vv.y);
                Vt[(c4 + 2) * FVPAD + row] = __float2half(vv.z);
                Vt[(c4 + 3) * FVPAD + row] = __float2half(vv.w);
            }
        }
        __syncthreads();

        float s[8][4];
#pragma unroll
        for (int nt = 0; nt < 8; nt++)
#pragma unroll
            for (int r = 0; r < 4; r++) s[nt][r] = 0.0f;

#pragma unroll
        for (int ks = 0; ks < 8; ks++) {
            const int kc = ks * 8 + tg;
            const int r0 = (wrow + g) * FQPAD;
            const int r1 = r0 + 8 * FQPAD;
            uint32_t ah[4], al[4];
            ah[0] = Qhi[r0 + kc];     ah[1] = Qhi[r1 + kc];
            ah[2] = Qhi[r0 + kc + 4]; ah[3] = Qhi[r1 + kc + 4];
            al[0] = Qlo[r0 + kc];     al[1] = Qlo[r1 + kc];
            al[2] = Qlo[r0 + kc + 4]; al[3] = Qlo[r1 + kc + 4];
#pragma unroll
            for (int nt = 0; nt < 8; nt++) {
                const int kr = (nt * 8 + g) * FQPAD;
                uint32_t bh2[2], bl2[2];
                bh2[0] = Khi[kr + kc]; bh2[1] = Khi[kr + kc + 4];
                bl2[0] = Klo[kr + kc]; bl2[1] = Klo[kr + kc + 4];
                mma_tf32(s[nt], ah, bh2);
                mma_tf32(s[nt], al, bh2);
                mma_tf32(s[nt], ah, bl2);
            }
        }

        if (kt >= ntiles - 2) {
            const int rl0 = q0 + wrow + g;
            const int rl1 = rl0 + 8;
#pragma unroll
            for (int nt = 0; nt < 8; nt++) {
                const int c0 = k0 + nt * 8 + 2 * tg;
                if (c0 > rl0)     s[nt][0] = -1e30f;
                if (c0 + 1 > rl0) s[nt][1] = -1e30f;
                if (c0 > rl1)     s[nt][2] = -1e30f;
                if (c0 + 1 > rl1) s[nt][3] = -1e30f;
            }
        }

        float mx0 = -1e30f, mx1 = -1e30f;
#pragma unroll
        for (int nt = 0; nt < 8; nt++) {
            mx0 = fmaxf(mx0, fmaxf(s[nt][0], s[nt][1]));
            mx1 = fmaxf(mx1, fmaxf(s[nt][2], s[nt][3]));
        }
        mx0 = fmaxf(mx0, __shfl_xor_sync(0xffffffffu, mx0, 1));
        mx0 = fmaxf(mx0, __shfl_xor_sync(0xffffffffu, mx0, 2));
        mx1 = fmaxf(mx1, __shfl_xor_sync(0xffffffffu, mx1, 1));
        mx1 = fmaxf(mx1, __shfl_xor_sync(0xffffffffu, mx1, 2));

        const float mn0 = fmaxf(m0r, mx0);
        const float mn1 = fmaxf(m1r, mx1);
        const float al0 = __expf(m0r - mn0);
        const float al1 = __expf(m1r - mn1);

        uint32_t ph0[8], ph1[8];
        float rs0 = 0.0f, rs1 = 0.0f;
#pragma unroll
        for (int nt = 0; nt < 8; nt++) {
            float p0 = __expf(s[nt][0] - mn0);
            float p1 = __expf(s[nt][1] - mn0);
            float p2 = __expf(s[nt][2] - mn1);
            float p3 = __expf(s[nt][3] - mn1);
            rs0 += p0 + p1;
            rs1 += p2 + p3;
            __half2 h0 = __floats2half2_rn(p0, p1);
            __half2 h1 = __floats2half2_rn(p2, p3);
            ph0[nt] = *(uint32_t*)&h0;
            ph1[nt] = *(uint32_t*)&h1;
        }
        rs0 += __shfl_xor_sync(0xffffffffu, rs0, 1);
        rs0 += __shfl_xor_sync(0xffffffffu, rs0, 2);
        rs1 += __shfl_xor_sync(0xffffffffu, rs1, 1);
        rs1 += __shfl_xor_sync(0xffffffffu, rs1, 2);

        l0r = l0r * al0 + rs0;
        l1r = l1r * al1 + rs1;
        m0r = mn0;
        m1r = mn1;

#pragma unroll
        for (int nt = 0; nt < 8; nt++) {
            o[nt][0] *= al0; o[nt][1] *= al0;
            o[nt][2] *= al1; o[nt][3] *= al1;
        }

#pragma unroll
        for (int kc = 0; kc < 4; kc++) {
            const uint32_t a0 = ph0[2 * kc];
            const uint32_t a1 = ph1[2 * kc];
            const uint32_t a2 = ph0[2 * kc + 1];
            const uint32_t a3 = ph1[2 * kc + 1];
#pragma unroll
            for (int ntd = 0; ntd < 8; ntd++) {
                const int vrow = (ntd * 8 + g) * FVPAD + kc * 16 + 2 * tg;
                const uint32_t b0 = *(const uint32_t*)&Vt[vrow];
                const uint32_t b1 = *(const uint32_t*)&Vt[vrow + 8];
                mma_f16(o[ntd], a0, a1, a2, a3, b0, b1);
            }
        }
    }

    const float inv0 = 1.0f / l0r;
    const float inv1 = 1.0f / l1r;
    const int row0 = q0 + wrow + g;
    const int row1 = row0 + 8;
#pragma unroll
    for (int nt = 0; nt < 8; nt++) {
        const int col = nt * 8 + 2 * tg;
        float2 v0 = make_float2(o[nt][0] * inv0, o[nt][1] * inv0);
        float2 v1 = make_float2(o[nt][2] * inv1, o[nt][3] * inv1);
        *(float2*)&O[base + (size_t)row0 * DD + col] = v0;
        *(float2*)&O[base + (size_t)row1 * DD + col] = v1;
    }
}

// ---------------------------------------------------------------------------
// Launch
// ---------------------------------------------------------------------------
extern "C" void kernel_launch(void* const* d_in, const int* in_sizes, int n_in,
                              void* d_out, int out_size)
{
    const float* q  = (const float*)d_in[0];
    const float* k  = (const float*)d_in[1];
    const float* v  = (const float*)d_in[2];
    // d_in[3] = mask: exactly triu(k=1) causal; handled analytically.
    const float* wq = (const float*)d_in[4];
    const float* wk = (const float*)d_in[5];
    const float* wv = (const float*)d_in[6];
    const float* wo = (const float*)d_in[7];
    const float* bo = (const float*)d_in[8];
    float* out = (float*)d_out;

    float *gq, *gk, *gv, *gc;
    cudaGetSymbolAddress((void**)&gq, g_Q);
    cudaGetSymbolAddress((void**)&gk, g_K);
    cudaGetSymbolAddress((void**)&gv, g_V);
    cudaGetSymbolAddress((void**)&gc, g_ctx);

    cudaFuncSetAttribute(flash_mma_kernel,
                         cudaFuncAttributeMaxDynamicSharedMemorySize, FSMEM_BYTES);
    cudaFuncSetAttribute(gemm_qkv_kernel,
                         cudaFuncAttributeMaxDynamicSharedMemorySize, GS_BYTES);
    cudaFuncSetAttribute(gemm_out_kernel,
                         cudaFuncAttributeMaxDynamicSharedMemorySize, GS_BYTES);

    dim3 qkv_grid(3 * (DD / TBN), MM / TBM);   // (24, 32)
    gemm_qkv_kernel<<<qkv_grid, 256, GS_BYTES>>>(q, k, v, wq, wk, wv, gq, gk, gv);

    dim3 flash_grid(SS / F2BM, BB * HH);       // (16, 32)
    flash_mma_kernel<<<flash_grid, 256, FSMEM_BYTES>>>(gq, gk, gv, gc);

    dim3 out_grid(DD / TBN, MM / TBM);         // (8, 32)
    gemm_out_kernel<<<out_grid, 256, GS_BYTES>>>(gc, wo, out, bo);
}

// round 6
// speedup vs baseline: 4.5215x; 1.1222x over previous
#include <cuda_runtime.h>
#include <cuda_fp16.h>
#include <cuda_bf16.h>
#include <cstdint>

// Problem constants (fixed by the reference)
#define BB 2
#define SS 2048
#define DD 1024
#define HH 16
#define DK 64
#define MM (BB * SS)   // 4096 rows for the projection GEMMs

// ---------------------------------------------------------------------------
// Scratch (allocation-free rule: __device__ globals)
// ---------------------------------------------------------------------------
__device__ float g_Q[MM * DD];
__device__ float g_K[MM * DD];
__device__ float g_V[MM * DD];
__device__ float g_ctx[MM * DD];

// ---------------------------------------------------------------------------
// helpers
// ---------------------------------------------------------------------------
__device__ __forceinline__ uint32_t f2tf32(float x) {
    uint32_t r;
    asm("cvt.rna.tf32.f32 %0, %1;" : "=r"(r) : "f"(x));
    return r;
}

__device__ __forceinline__ void mma_tf32(float* c, const uint32_t* a, const uint32_t* b) {
    asm volatile(
        "mma.sync.aligned.m16n8k8.row.col.f32.tf32.tf32.f32 "
        "{%0,%1,%2,%3}, {%4,%5,%6,%7}, {%8,%9}, {%0,%1,%2,%3};\n"
        : "+f"(c[0]), "+f"(c[1]), "+f"(c[2]), "+f"(c[3])
        : "r"(a[0]), "r"(a[1]), "r"(a[2]), "r"(a[3]), "r"(b[0]), "r"(b[1]));
}

__device__ __forceinline__ void mma_f16(float* c, uint32_t a0, uint32_t a1,
                                        uint32_t a2, uint32_t a3,
                                        uint32_t b0, uint32_t b1) {
    asm volatile(
        "mma.sync.aligned.m16n8k16.row.col.f32.f16.f16.f32 "
        "{%0,%1,%2,%3}, {%4,%5,%6,%7}, {%8,%9}, {%0,%1,%2,%3};\n"
        : "+f"(c[0]), "+f"(c[1]), "+f"(c[2]), "+f"(c[3])
        : "r"(a0), "r"(a1), "r"(a2), "r"(a3), "r"(b0), "r"(b1));
}

// fp16 hi/lo error-compensated split of two floats, packed as half2 words
__device__ __forceinline__ void split_h2(float x, float y, uint32_t& h, uint32_t& l) {
    __half2 hh = __floats2half2_rn(x, y);
    float2 ff = __half22float2(hh);
    __half2 ll = __floats2half2_rn(x - ff.x, y - ff.y);
    h = *(uint32_t*)&hh;
    l = *(uint32_t*)&ll;
}

__device__ __forceinline__ void cp_async16(uint32_t saddr, const void* gptr) {
    asm volatile("cp.async.cg.shared.global [%0], [%1], 16;\n"
                 :: "r"(saddr), "l"(gptr));
}
__device__ __forceinline__ void cp_commit() {
    asm volatile("cp.async.commit_group;\n");
}
template <int N>
__device__ __forceinline__ void cp_wait() {
    asm volatile("cp.async.wait_group %0;\n" :: "n"(N) : "memory");
}

// ---------------------------------------------------------------------------
// GEMM: C = A[M,K] @ W[N,K]^T (+bias), tf32 mma, 128x128x16 tile,
// 4-stage cp.async pipeline, one __syncthreads per K-tile. (unchanged R5)
// ---------------------------------------------------------------------------
#define TBM 128
#define TBN 128
#define TBK 16
#define TPAD 20
#define GSTAGES 4
#define GSTAGE_WORDS ((TBM + TBN) * TPAD)
#define GS_BYTES (GSTAGES * GSTAGE_WORDS * 4)

__device__ __forceinline__ void gemm_body2(
    const float* __restrict__ A, const float* __restrict__ W,
    float* __restrict__ C, const float* __restrict__ bias,
    int m0, int n0, int Ndim, int Kdim, float* sm)
{
    const int tid  = threadIdx.x;
    const int lane = tid & 31;
    const int warp = tid >> 5;
    const int wm = (warp >> 2) * 64;
    const int wn = (warp & 3) * 32;
    const int g  = lane >> 2;
    const int tg = lane & 3;
    const int lrow = tid >> 2;
    const int lcol = (tid & 3) << 2;

    const float* Aptr = A + (size_t)(m0 + lrow) * Kdim + lcol;
    const float* Wptr = W + (size_t)(n0 + lrow) * Kdim + lcol;
    const size_t rstep = (size_t)64 * Kdim;

    const uint32_t smbase = (uint32_t)__cvta_generic_to_shared(sm);
    const uint32_t a_off0 = (uint32_t)(lrow * TPAD + lcol) * 4;
    const uint32_t a_off1 = (uint32_t)((lrow + 64) * TPAD + lcol) * 4;
    const uint32_t w_base = (uint32_t)(TBM * TPAD) * 4;

    const int steps = Kdim / TBK;

#pragma unroll
    for (int st = 0; st < GSTAGES - 1; st++) {
        const uint32_t sb = smbase + st * (GSTAGE_WORDS * 4);
        const float* ap = Aptr + st * TBK;
        const float* wp = Wptr + st * TBK;
        cp_async16(sb + a_off0, ap);
        cp_async16(sb + a_off1, ap + rstep);
        cp_async16(sb + w_base + a_off0, wp);
        cp_async16(sb + w_base + a_off1, wp + rstep);
        cp_commit();
    }

    float c[4][4][4];
#pragma unroll
    for (int im = 0; im < 4; im++)
#pragma unroll
        for (int in = 0; in < 4; in++)
#pragma unroll
            for (int r = 0; r < 4; r++) c[im][in][r] = 0.0f;

    for (int kt = 0; kt < steps; kt++) {
        cp_wait<GSTAGES - 2>();
        __syncthreads();

        if (kt + GSTAGES - 1 < steps) {
            const int st = (kt + GSTAGES - 1) % GSTAGES;
            const uint32_t sb = smbase + st * (GSTAGE_WORDS * 4);
            const float* ap = Aptr + (kt + GSTAGES - 1) * TBK;
            const float* wp = Wptr + (kt + GSTAGES - 1) * TBK;
            cp_async16(sb + a_off0, ap);
            cp_async16(sb + a_off1, ap + rstep);
            cp_async16(sb + w_base + a_off0, wp);
            cp_async16(sb + w_base + a_off1, wp + rstep);
        }
        cp_commit();

        const float* Ab = sm + (kt % GSTAGES) * GSTAGE_WORDS;
        const float* Wb = Ab + TBM * TPAD;

#pragma unroll
        for (int ks = 0; ks < 2; ks++) {
            const int k0 = ks * 8;
            uint32_t af[4][4], bf[4][2];
#pragma unroll
            for (int im = 0; im < 4; im++) {
                const int r = wm + im * 16 + g;
                af[im][0] = f2tf32(Ab[r * TPAD + k0 + tg]);
                af[im][1] = f2tf32(Ab[(r + 8) * TPAD + k0 + tg]);
                af[im][2] = f2tf32(Ab[r * TPAD + k0 + tg + 4]);
                af[im][3] = f2tf32(Ab[(r + 8) * TPAD + k0 + tg + 4]);
            }
#pragma unroll
            for (int in = 0; in < 4; in++) {
                const int nr = wn + in * 8 + g;
                bf[in][0] = f2tf32(Wb[nr * TPAD + k0 + tg]);
                bf[in][1] = f2tf32(Wb[nr * TPAD + k0 + tg + 4]);
            }
#pragma unroll
            for (int im = 0; im < 4; im++)
#pragma unroll
                for (int in = 0; in < 4; in++)
                    mma_tf32(c[im][in], af[im], bf[in]);
        }
    }

#pragma unroll
    for (int im = 0; im < 4; im++) {
        const int r = m0 + wm + im * 16 + g;
#pragma unroll
        for (int in = 0; in < 4; in++) {
            const int col = n0 + wn + in * 8 + (tg << 1);
            float b0v = 0.0f, b1v = 0.0f;
            if (bias) { b0v = bias[col]; b1v = bias[col + 1]; }
            float2 v0 = make_float2(c[im][in][0] + b0v, c[im][in][1] + b1v);
            float2 v1 = make_float2(c[im][in][2] + b0v, c[im][in][3] + b1v);
            *(float2*)&C[(size_t)r * Ndim + col] = v0;
            *(float2*)&C[(size_t)(r + 8) * Ndim + col] = v1;
        }
    }
}

__global__ __launch_bounds__(256) void gemm_qkv_kernel(
    const float* __restrict__ Aq, const float* __restrict__ Ak, const float* __restrict__ Av,
    const float* __restrict__ Wq, const float* __restrict__ Wk, const float* __restrict__ Wv,
    float* __restrict__ Cq, float* __restrict__ Ck, float* __restrict__ Cv)
{
    extern __shared__ float gsm[];
    const int sel  = blockIdx.x >> 3;
    const int nblk = blockIdx.x & 7;
    const float* A = (sel == 0) ? Aq : (sel == 1) ? Ak : Av;
    const float* W = (sel == 0) ? Wq : (sel == 1) ? Wk : Wv;
    float*       C = (sel == 0) ? Cq : (sel == 1) ? Ck : Cv;
    gemm_body2(A, W, C, nullptr, blockIdx.y * TBM, nblk * TBN, DD, DD, gsm);
}

__global__ __launch_bounds__(256) void gemm_out_kernel(
    const float* __restrict__ A, const float* __restrict__ W,
    float* __restrict__ C, const float* __restrict__ bias)
{
    extern __shared__ float gsm[];
    gemm_body2(A, W, C, bias, blockIdx.y * TBM, blockIdx.x * TBN, DD, DD, gsm);
}

// ---------------------------------------------------------------------------
// Tensor-core flash attention (causal).
// BM=128 q rows (8 warps x m16), BN=64 keys/iter, DK=64.
// QK^T: fp16 hi/lo 3-pass mma.m16n8k16 (fp32-grade scores, half the tensor
// instructions of 3xTF32-k8). 1/sqrt(DK) applied to S post-mma.
// P@V: fp16 mma, P resident in registers. K/V double-buffered via cp.async.
// ---------------------------------------------------------------------------
#define F2BM 128
#define QSTR 36    // half2-words per row: 32 + 4 pad (4 mod 32 -> conflict-free)
#define FVPAD 72   // halves per Vt row

// word offsets into dynamic smem
#define OQH 0
#define OQL (F2BM * QSTR)              // 4608
#define OKH (2 * F2BM * QSTR)          // 9216
#define OKL (OKH + 64 * QSTR)          // 11520
#define OVT (OKL + 64 * QSTR)          // 13824 (half region)
#define ORAW (OVT + (64 * FVPAD) / 2)  // 16128
#define RAWSTRIDE 8192                 // words per stage (K 4096 + V 4096)
#define FSMEM_BYTES ((ORAW + 2 * RAWSTRIDE) * 4)   // 130048 B

__global__ __launch_bounds__(256, 1) void flash_mma_kernel(
    const float* __restrict__ Q, const float* __restrict__ K,
    const float* __restrict__ V, float* __restrict__ O)
{
    extern __shared__ uint32_t fsm[];
    uint32_t* Qh = fsm + OQH;
    uint32_t* Ql = fsm + OQL;
    uint32_t* Kh = fsm + OKH;
    uint32_t* Kl = fsm + OKL;
    __half*   Vt = (__half*)(fsm + OVT);

    const int bh = blockIdx.y;
    const int b  = bh / HH;
    const int h  = bh % HH;
    const int qtile = (gridDim.x - 1) - blockIdx.x;   // heavy blocks first
    const int q0 = qtile * F2BM;

    const int tid  = threadIdx.x;
    const int lane = tid & 31;
    const int warp = tid >> 5;
    const int g  = lane >> 2;
    const int tg = lane & 3;
    const int wrow = warp * 16;

    const size_t base = (size_t)b * SS * DD + (size_t)h * DK;
    const float* Kg = K + base;
    const float* Vg = V + base;

    const int ntiles = 2 * qtile + 2;

    // ---- cp.async tile 0 ----
    {
        uint32_t rawk = (uint32_t)__cvta_generic_to_shared(fsm + ORAW);
#pragma unroll
        for (int j = 0; j < 4; j++) {
            const int i = tid + j * 256;
            const int row = i >> 4;
            const int c4  = (i & 15) << 2;
            cp_async16(rawk + (uint32_t)(row * 64 + c4) * 4,
                       Kg + (size_t)row * DD + c4);
            cp_async16(rawk + 16384u + (uint32_t)(row * 64 + c4) * 4,
                       Vg + (size_t)row * DD + c4);
        }
        cp_commit();
    }

    // ---- load Q tile, fp16 hi/lo split (unscaled; scale applied to S) ----
    {
        const float* Qg = Q + base + (size_t)q0 * DD;
#pragma unroll
        for (int i = tid; i < F2BM * 16; i += 256) {
            const int row = i >> 4;
            const int c4  = (i & 15) << 2;
            float4 v = *(const float4*)(Qg + (size_t)row * DD + c4);
            uint32_t h01, l01, h23, l23;
            split_h2(v.x, v.y, h01, l01);
            split_h2(v.z, v.w, h23, l23);
            const int wi = row * QSTR + (c4 >> 1);
            Qh[wi] = h01; Qh[wi + 1] = h23;
            Ql[wi] = l01; Ql[wi + 1] = l23;
        }
    }

    float o[8][4];
#pragma unroll
    for (int nt = 0; nt < 8; nt++)
#pragma unroll
        for (int r = 0; r < 4; r++) o[nt][r] = 0.0f;
    float m0r = -1e30f, m1r = -1e30f;
    float l0r = 0.0f,  l1r = 0.0f;

    for (int kt = 0; kt < ntiles; kt++) {
        const int k0 = kt * 64;

        // ---- issue next tile, wait for current ----
        if (kt + 1 < ntiles) {
            const int k0n = (kt + 1) * 64;
            uint32_t rawk = (uint32_t)__cvta_generic_to_shared(
                fsm + ORAW + ((kt + 1) & 1) * RAWSTRIDE);
#pragma unroll
            for (int j = 0; j < 4; j++) {
                const int i = tid + j * 256;
                const int row = i >> 4;
                const int c4  = (i & 15) << 2;
                cp_async16(rawk + (uint32_t)(row * 64 + c4) * 4,
                           Kg + (size_t)(k0n + row) * DD + c4);
                cp_async16(rawk + 16384u + (uint32_t)(row * 64 + c4) * 4,
                           Vg + (size_t)(k0n + row) * DD + c4);
            }
            cp_commit();
            cp_wait<1>();
        } else {
            cp_wait<0>();
        }
        __syncthreads();

        // ---- convert raw[kt] -> Kh/Kl (fp16 split) and Vt (fp16 transposed) ----
        {
            const float* rk = (const float*)(fsm + ORAW + (kt & 1) * RAWSTRIDE);
            const float* rv = rk + 4096;
#pragma unroll
            for (int j = 0; j < 4; j++) {
                const int i = tid + j * 256;
                const int row = i >> 4;
                const int c4  = (i & 15) << 2;
                float4 kv = *(const float4*)(rk + row * 64 + c4);
                uint32_t h01, l01, h23, l23;
                split_h2(kv.x, kv.y, h01, l01);
                split_h2(kv.z, kv.w, h23, l23);
                const int wi = row * QSTR + (c4 >> 1);
                Kh[wi] = h01; Kh[wi + 1] = h23;
                Kl[wi] = l01; Kl[wi + 1] = l23;

                float4 vv = *(const float4*)(rv + row * 64 + c4);
                Vt[(c4 + 0) * FVPAD + row] = __float2half(vv.x);
                Vt[(c4 + 1) * FVPAD + row] = __float2half(vv.y);
                Vt[(c4 + 2) * FVPAD + row] = __float2half(vv.z);
                Vt[(c4 + 3) * FVPAD + row] = __float2half(vv.w);
            }
        }
        __syncthreads();

        // ---- S = Q K^T (fp16 3-pass: qh*kh + ql*kh + qh*kl) ----
        float s[8][4];
#pragma unroll
        for (int nt = 0; nt < 8; nt++)
#pragma unroll
            for (int r = 0; r < 4; r++) s[nt][r] = 0.0f;

#pragma unroll
        for (int ks = 0; ks < 4; ks++) {
            const int wq = 8 * ks + tg;
            const int r0 = (wrow + g) * QSTR;
            const int r1 = r0 + 8 * QSTR;
            const uint32_t ah0 = Qh[r0 + wq],     ah1 = Qh[r1 + wq];
            const uint32_t ah2 = Qh[r0 + wq + 4], ah3 = Qh[r1 + wq + 4];
            const uint32_t al0 = Ql[r0 + wq],     al1 = Ql[r1 + wq];
            const uint32_t al2 = Ql[r0 + wq + 4], al3 = Ql[r1 + wq + 4];
#pragma unroll
            for (int nt = 0; nt < 8; nt++) {
                const int kr = (nt * 8 + g) * QSTR;
                const uint32_t bh0 = Kh[kr + wq], bh1 = Kh[kr + wq + 4];
                const uint32_t bl0 = Kl[kr + wq], bl1 = Kl[kr + wq + 4];
                mma_f16(s[nt], ah0, ah1, ah2, ah3, bh0, bh1);
                mma_f16(s[nt], al0, al1, al2, al3, bh0, bh1);
                mma_f16(s[nt], ah0, ah1, ah2, ah3, bl0, bl1);
            }
        }

        // ---- scale by 1/sqrt(DK) ----
#pragma unroll
        for (int nt = 0; nt < 8; nt++) {
            s[nt][0] *= 0.125f; s[nt][1] *= 0.125f;
            s[nt][2] *= 0.125f; s[nt][3] *= 0.125f;
        }

        // ---- causal mask: only the last two key tiles cross the diagonal ----
        if (kt >= ntiles - 2) {
            const int rl0 = q0 + wrow + g;
            const int rl1 = rl0 + 8;
#pragma unroll
            for (int nt = 0; nt < 8; nt++) {
                const int c0 = k0 + nt * 8 + 2 * tg;
                if (c0 > rl0)     s[nt][0] = -1e30f;
                if (c0 + 1 > rl0) s[nt][1] = -1e30f;
                if (c0 > rl1)     s[nt][2] = -1e30f;
                if (c0 + 1 > rl1) s[nt][3] = -1e30f;
            }
        }

        // ---- online softmax ----
        float mx0 = -1e30f, mx1 = -1e30f;
#pragma unroll
        for (int nt = 0; nt < 8; nt++) {
            mx0 = fmaxf(mx0, fmaxf(s[nt][0], s[nt][1]));
            mx1 = fmaxf(mx1, fmaxf(s[nt][2], s[nt][3]));
        }
        mx0 = fmaxf(mx0, __shfl_xor_sync(0xffffffffu, mx0, 1));
        mx0 = fmaxf(mx0, __shfl_xor_sync(0xffffffffu, mx0, 2));
        mx1 = fmaxf(mx1, __shfl_xor_sync(0xffffffffu, mx1, 1));
        mx1 = fmaxf(mx1, __shfl_xor_sync(0xffffffffu, mx1, 2));

        const float mn0 = fmaxf(m0r, mx0);
        const float mn1 = fmaxf(m1r, mx1);
        const float al0 = __expf(m0r - mn0);
        const float al1 = __expf(m1r - mn1);

        uint32_t ph0[8], ph1[8];
        float rs0 = 0.0f, rs1 = 0.0f;
#pragma unroll
        for (int nt = 0; nt < 8; nt++) {
            float p0 = __expf(s[nt][0] - mn0);
            float p1 = __expf(s[nt][1] - mn0);
            float p2 = __expf(s[nt][2] - mn1);
            float p3 = __expf(s[nt][3] - mn1);
            rs0 += p0 + p1;
            rs1 += p2 + p3;
            __half2 h0 = __floats2half2_rn(p0, p1);
            __half2 h1 = __floats2half2_rn(p2, p3);
            ph0[nt] = *(uint32_t*)&h0;
            ph1[nt] = *(uint32_t*)&h1;
        }
        rs0 += __shfl_xor_sync(0xffffffffu, rs0, 1);
        rs0 += __shfl_xor_sync(0xffffffffu, rs0, 2);
        rs1 += __shfl_xor_sync(0xffffffffu, rs1, 1);
        rs1 += __shfl_xor_sync(0xffffffffu, rs1, 2);

        l0r = l0r * al0 + rs0;
        l1r = l1r * al1 + rs1;
        m0r = mn0;
        m1r = mn1;

#pragma unroll
        for (int nt = 0; nt < 8; nt++) {
            o[nt][0] *= al0; o[nt][1] *= al0;
            o[nt][2] *= al1; o[nt][3] *= al1;
        }

        // ---- O += P @ V (fp16 mma, P from registers) ----
#pragma unroll
        for (int kc = 0; kc < 4; kc++) {
            const uint32_t a0 = ph0[2 * kc];
            const uint32_t a1 = ph1[2 * kc];
            const uint32_t a2 = ph0[2 * kc + 1];
            const uint32_t a3 = ph1[2 * kc + 1];
#pragma unroll
            for (int ntd = 0; ntd < 8; ntd++) {
                const int vrow = (ntd * 8 + g) * FVPAD + kc * 16 + 2 * tg;
                const uint32_t b0 = *(const uint32_t*)&Vt[vrow];
                const uint32_t b1 = *(const uint32_t*)&Vt[vrow + 8];
                mma_f16(o[ntd], a0, a1, a2, a3, b0, b1);
            }
        }
    }

    // ---- epilogue ----
    const float inv0 = 1.0f / l0r;
    const float inv1 = 1.0f / l1r;
    const int row0 = q0 + wrow + g;
    const int row1 = row0 + 8;
#pragma unroll
    for (int nt = 0; nt < 8; nt++) {
        const int col = nt * 8 + 2 * tg;
        float2 v0 = make_float2(o[nt][0] * inv0, o[nt][1] * inv0);
        float2 v1 = make_float2(o[nt][2] * inv1, o[nt][3] * inv1);
        *(float2*)&O[base + (size_t)row0 * DD + col] = v0;
        *(float2*)&O[base + (size_t)row1 * DD + col] = v1;
    }
}

// ---------------------------------------------------------------------------
// Launch
// ---------------------------------------------------------------------------
extern "C" void kernel_launch(void* const* d_in, const int* in_sizes, int n_in,
                              void* d_out, int out_size)
{
    const float* q  = (const float*)d_in[0];
    const float* k  = (const float*)d_in[1];
    const float* v  = (const float*)d_in[2];
    // d_in[3] = mask: exactly triu(k=1) causal; handled analytically.
    const float* wq = (const float*)d_in[4];
    const float* wk = (const float*)d_in[5];
    const float* wv = (const float*)d_in[6];
    const float* wo = (const float*)d_in[7];
    const float* bo = (const float*)d_in[8];
    float* out = (float*)d_out;

    float *gq, *gk, *gv, *gc;
    cudaGetSymbolAddress((void**)&gq, g_Q);
    cudaGetSymbolAddress((void**)&gk, g_K);
    cudaGetSymbolAddress((void**)&gv, g_V);
    cudaGetSymbolAddress((void**)&gc, g_ctx);

    cudaFuncSetAttribute(flash_mma_kernel,
                         cudaFuncAttributeMaxDynamicSharedMemorySize, FSMEM_BYTES);
    cudaFuncSetAttribute(gemm_qkv_kernel,
                         cudaFuncAttributeMaxDynamicSharedMemorySize, GS_BYTES);
    cudaFuncSetAttribute(gemm_out_kernel,
                         cudaFuncAttributeMaxDynamicSharedMemorySize, GS_BYTES);

    dim3 qkv_grid(3 * (DD / TBN), MM / TBM);   // (24, 32)
    gemm_qkv_kernel<<<qkv_grid, 256, GS_BYTES>>>(q, k, v, wq, wk, wv, gq, gk, gv);

    dim3 flash_grid(SS / F2BM, BB * HH);       // (16, 32)
    flash_mma_kernel<<<flash_grid, 256, FSMEM_BYTES>>>(gq, gk, gv, gc);

    dim3 out_grid(DD / TBN, MM / TBM);         // (8, 32)
    gemm_out_kernel<<<out_grid, 256, GS_BYTES>>>(gc, wo, out, bo);
}